// round 14
// baseline (speedup 1.0000x reference)
#include <cuda_runtime.h>
#include <cuda_bf16.h>
#include <float.h>
#include <stdint.h>

#define NN   50000
#define EE   250000
#define ET   300000
#define NG   64
#define MBPAD 3128   // ceil(50048/16): padded m16-block count (zero-init tail)

// ---------------------------------------------------------------------------
// Device scratch
// ---------------------------------------------------------------------------
__device__ __align__(16) float    g_P[(size_t)NN * 512];          // h2 / h3 (fp32)
__device__ __align__(16) uint32_t g_Qh[(size_t)MBPAD * 64 * 128]; // A frag hi / o3 fp32
__device__ __align__(16) uint32_t g_Ql[(size_t)MBPAD * 64 * 128]; // A frag lo
__device__ __align__(16) float    g_z[(size_t)NN * 88];

__device__ __align__(16) uint32_t g_B2h[64 * 64 * 64];   // W2 frag [kb][nb][64]
__device__ __align__(16) uint32_t g_B2l[64 * 64 * 64];
__device__ __align__(16) uint32_t g_B3h[32 * 16 * 64];
__device__ __align__(16) uint32_t g_B3l[32 * 16 * 64];

__device__ float g_als[NN * 8];
__device__ float g_ald[NN * 8];
__device__ float g_ws[11 * 8];
__device__ float g_wd[11 * 8];

__device__ int   g_srcS[ET];
__device__ int   g_deg[NN];
__device__ int   g_off[NN + 1];
__device__ int   g_cur[NN];
__device__ int   g_bsum[64];
__device__ int   g_boff[64];

__device__ int g_ei64;
__device__ int g_b64;

__device__ __forceinline__ int clampN(int v) {
    return (v < 0) ? 0 : ((v >= NN) ? NN - 1 : v);
}

// bf16 hi/lo split of two adjacent-k values, packed (lo halfword = even k)
__device__ __forceinline__ void split_pack(float v0, float v1, uint32_t& ph, uint32_t& pl) {
    __nv_bfloat16 h0 = __float2bfloat16(v0);
    __nv_bfloat16 h1 = __float2bfloat16(v1);
    float r0 = v0 - __bfloat162float(h0);
    float r1 = v1 - __bfloat162float(h1);
    __nv_bfloat16 l0 = __float2bfloat16(r0);
    __nv_bfloat16 l1 = __float2bfloat16(r1);
    __nv_bfloat162 H = __halves2bfloat162(h0, h1);
    __nv_bfloat162 L = __halves2bfloat162(l0, l1);
    ph = *reinterpret_cast<uint32_t*>(&H);
    pl = *reinterpret_cast<uint32_t*>(&L);
}

// A fragment index: (n, c) -> u32 index in [mb][kb][128] frag array (KB16 kblocks)
__device__ __forceinline__ size_t a_frag_idx(int n, int c, int KB16) {
    int mb = n >> 4, rr = n & 15, kb = c >> 3, c8 = c & 7;
    int lane = (rr & 7) * 4 + (c8 & 3);
    int slot = (rr >> 3) + 2 * (c8 >> 2);
    return ((size_t)mb * KB16 + kb) * 128 + lane * 4 + slot;
}

// ---------------------------------------------------------------------------
// Parallel dtype detection
// ---------------------------------------------------------------------------
__global__ void k_detect(const int* __restrict__ ei, const int* __restrict__ batch) {
    int t = threadIdx.x;
    int ok1 = (ei[2 * t + 1] == 0);
    int idx = NN - 1024 + t;
    int ok2 = ((idx & 1) == 0) || (batch[idx] == 0);
    int a1 = __syncthreads_and(ok1);
    int a2 = __syncthreads_and(ok2);
    if (t == 0) { g_ei64 = a1; g_b64 = a2; }
}

__device__ __forceinline__ int ld_ei(const int* __restrict__ ei, int i) {
    return g_ei64 ? ei[2 * i] : ei[i];
}
__device__ __forceinline__ int ld_b(const int* __restrict__ b, int i) {
    return g_b64 ? b[2 * i] : b[i];
}

// ---------------------------------------------------------------------------
// CSR build
// ---------------------------------------------------------------------------
__global__ void k_zero_deg() {
    int i = blockIdx.x * blockDim.x + threadIdx.x;
    if (i < NN) g_deg[i] = 0;
}

__global__ void k_count(const int* __restrict__ ei) {
    int e = blockIdx.x * blockDim.x + threadIdx.x;
    if (e >= ET) return;
    int dst = (e < EE) ? clampN(ld_ei(ei, EE + e)) : (e - EE);
    atomicAdd(&g_deg[dst], 1);
}

__global__ void k_scan1() {
    int b = blockIdx.x, t = threadIdx.x;
    int i = b * 1000 + t;
    int v = (t < 1000 && i < NN) ? g_deg[i] : 0;
#pragma unroll
    for (int o = 16; o > 0; o >>= 1) v += __shfl_down_sync(0xFFFFFFFFu, v, o);
    __shared__ int w[32];
    int lane = t & 31, wid = t >> 5;
    if (lane == 0) w[wid] = v;
    __syncthreads();
    if (wid == 0) {
        int x = w[lane];
#pragma unroll
        for (int o = 16; o > 0; o >>= 1) x += __shfl_down_sync(0xFFFFFFFFu, x, o);
        if (lane == 0) g_bsum[b] = x;
    }
}

__global__ void k_scan2() {
    if (threadIdx.x != 0) return;
    int run = 0;
    for (int b = 0; b < 50; b++) { g_boff[b] = run; run += g_bsum[b]; }
    g_off[NN] = run;
}

__global__ void k_scan3() {
    int b = blockIdx.x, t = threadIdx.x;
    int i = b * 1000 + t;
    int v = (t < 1000 && i < NN) ? g_deg[i] : 0;
    int lane = t & 31, wid = t >> 5;
    int incl = v;
#pragma unroll
    for (int o = 1; o < 32; o <<= 1) {
        int u = __shfl_up_sync(0xFFFFFFFFu, incl, o);
        if (lane >= o) incl += u;
    }
    __shared__ int wl[32];
    if (lane == 31) wl[wid] = incl;
    __syncthreads();
    if (wid == 0) {
        int x = wl[lane];
#pragma unroll
        for (int o = 1; o < 32; o <<= 1) {
            int u = __shfl_up_sync(0xFFFFFFFFu, x, o);
            if (lane >= o) x += u;
        }
        wl[lane] = x;
    }
    __syncthreads();
    int excl = incl - v + ((wid > 0) ? wl[wid - 1] : 0);
    if (t < 1000 && i < NN) {
        int off = g_boff[b] + excl;
        g_off[i] = off;
        g_cur[i] = off;
    }
}

__global__ void k_scatter(const int* __restrict__ ei) {
    int e = blockIdx.x * blockDim.x + threadIdx.x;
    if (e >= ET) return;
    int src, dst;
    if (e < EE) { src = clampN(ld_ei(ei, e)); dst = clampN(ld_ei(ei, EE + e)); }
    else        { src = e - EE;               dst = e - EE; }
    int pos = atomicAdd(&g_cur[dst], 1);
    if (pos >= 0 && pos < ET) g_srcS[pos] = src;
}

// ---------------------------------------------------------------------------
// Weight prep: pack W (KxM fp32) into fragment-major hi/lo [kb][nb][64]
// ---------------------------------------------------------------------------
__global__ void k_wprep(const float* __restrict__ W, uint32_t* __restrict__ Bh,
                        uint32_t* __restrict__ Bl, int KB16, int M) {
    int idx = blockIdx.x * blockDim.x + threadIdx.x;
    int NB = M >> 3;
    if (idx >= KB16 * NB * 64) return;
    int block = idx >> 6, r = idx & 63;
    int lane = r >> 1, slot = r & 1;
    int kb = block / NB, nb = block - kb * NB;
    int coll = lane >> 2, tg = lane & 3;
    int c8 = tg + slot * 4;
    int k2 = kb * 8 + c8;
    int m = nb * 8 + coll;
    float a0 = W[(size_t)(2 * k2) * M + m];
    float a1 = W[(size_t)(2 * k2 + 1) * M + m];
    uint32_t ph, pl;
    split_pack(a0, a1, ph, pl);
    Bh[idx] = ph;
    Bl[idx] = pl;
}

// ---------------------------------------------------------------------------
// Layer-1 algebraic path
// ---------------------------------------------------------------------------
__global__ void k_wsd(const float* __restrict__ W1, const float* __restrict__ a1s,
                      const float* __restrict__ a1d) {
    int t = threadIdx.x;
    if (t >= 88) return;
    int k = t / 8, h = t % 8;
    float ss = 0.f, sd = 0.f;
    const float* wrow = W1 + k * 1024 + h * 128;
    const float* asr  = a1s + h * 128;
    const float* adr  = a1d + h * 128;
    for (int c = 0; c < 128; c++) {
        float w = wrow[c];
        ss += w * asr[c];
        sd += w * adr[c];
    }
    g_ws[k * 8 + h] = ss;
    g_wd[k * 8 + h] = sd;
}

__global__ void k_alx(const float* __restrict__ x) {
    __shared__ float ws[88], wd[88];
    int t = threadIdx.x;
    if (t < 88) { ws[t] = g_ws[t]; wd[t] = g_wd[t]; }
    __syncthreads();
    int n = blockIdx.x * blockDim.x + t;
    if (n >= NN) return;
    float xv[11];
#pragma unroll
    for (int k = 0; k < 11; k++) xv[k] = x[n * 11 + k];
#pragma unroll
    for (int h = 0; h < 8; h++) {
        float ps = 0.f, pd = 0.f;
#pragma unroll
        for (int k = 0; k < 11; k++) {
            ps += xv[k] * ws[k * 8 + h];
            pd += xv[k] * wd[k * 8 + h];
        }
        g_als[n * 8 + h] = ps;
        g_ald[n * 8 + h] = pd;
    }
}

// Layer-1 aggregation + fused streaming softmax: warp per node.
__global__ void k_aggx(const float* __restrict__ x) {
    int gw = (blockIdx.x * blockDim.x + threadIdx.x) >> 5;
    if (gw >= NN) return;
    int lane = threadIdx.x & 31;
    int n = gw;
    float ad = (lane < 8) ? g_ald[n * 8 + lane] : 0.f;

    int s0 = g_off[n], s1 = g_off[n + 1];

    // phase A: streaming max + sum (lane < 8 <-> head)
    float m = -FLT_MAX, ssum = 0.f;
    for (int j = s0; j < s1; j++) {
        int src = g_srcS[j];
        if (lane < 8) {
            float e = g_als[src * 8 + lane] + ad;
            e = fmaxf(e, 0.2f * e);
            if (e > m) { ssum *= __expf(m - e); m = e; }
            ssum += __expf(e - m);
        }
    }
    float dv = 1.f / (ssum + 1e-16f);

    int i0 = lane, i1 = lane + 32, i2 = lane + 64;
    int h0 = i0 / 11, k0 = i0 - h0 * 11;
    int h1 = i1 / 11, k1 = i1 - h1 * 11;
    bool v2 = (i2 < 88);
    int h2 = v2 ? i2 / 11 : 0, k2 = v2 ? i2 - (i2 / 11) * 11 : 0;
    float z0 = 0.f, z1 = 0.f, z2 = 0.f;

    // phase B: normalize + accumulate
    for (int j = s0; j < s1; j++) {
        int src = g_srcS[j];
        float xv = (lane < 11) ? x[src * 11 + lane] : 0.f;
        float av = 0.f;
        if (lane < 8) {
            float e = g_als[src * 8 + lane] + ad;
            e = fmaxf(e, 0.2f * e);
            av = __expf(e - m) * dv;
        }
        float a0 = __shfl_sync(0xFFFFFFFFu, av, h0);
        float x0 = __shfl_sync(0xFFFFFFFFu, xv, k0);
        float a1 = __shfl_sync(0xFFFFFFFFu, av, h1);
        float x1 = __shfl_sync(0xFFFFFFFFu, xv, k1);
        float a2 = __shfl_sync(0xFFFFFFFFu, av, h2);
        float x2 = __shfl_sync(0xFFFFFFFFu, xv, k2);
        z0 += a0 * x0;
        z1 += a1 * x1;
        if (v2) z2 += a2 * x2;
    }
    g_z[(size_t)n * 88 + i0] = z0;
    g_z[(size_t)n * 88 + i1] = z1;
    if (v2) g_z[(size_t)n * 88 + i2] = z2;
}

// o1 projection; emits fragment-major bf16 hi/lo (A of GEMM2, KB16=64)
__global__ __launch_bounds__(256) void k_proj(const float* __restrict__ W1,
                                              const float* __restrict__ b1,
                                              uint32_t* __restrict__ oh,
                                              uint32_t* __restrict__ ol) {
    __shared__ float Wh[11][128];
    __shared__ float zt[64][11];
    int n0 = blockIdx.x * 64;
    int h = blockIdx.y;
    int t = threadIdx.x;
    for (int i = t; i < 11 * 128; i += 256) {
        int k = i >> 7, c = i & 127;
        Wh[k][c] = W1[k * 1024 + h * 128 + c];
    }
    for (int i = t; i < 64 * 11; i += 256) {
        int r = i / 11, k = i - r * 11;
        int n = n0 + r;
        zt[r][k] = (n < NN) ? g_z[(size_t)n * 88 + h * 11 + k] : 0.f;
    }
    __syncthreads();
    int c = t & 63;
    int rg = t >> 6;
    float bias0 = b1[h * 128 + 2 * c];
    float bias1 = b1[h * 128 + 2 * c + 1];
    int cg = h * 64 + c;
#pragma unroll 4
    for (int i = 0; i < 16; i++) {
        int r = rg * 16 + i;
        int n = n0 + r;
        if (n >= NN) break;
        float a0 = bias0, a1 = bias1;
#pragma unroll
        for (int k = 0; k < 11; k++) {
            float zz = zt[r][k];
            a0 += zz * Wh[k][2 * c];
            a1 += zz * Wh[k][2 * c + 1];
        }
        a0 = (a0 > 0.f) ? a0 : 0.01f * a0;
        a1 = (a1 > 0.f) ? a1 : 0.01f * a1;
        uint32_t ph, pl;
        split_pack(a0, a1, ph, pl);
        size_t idx = a_frag_idx(n, cg, 64);
        oh[idx] = ph;
        ol[idx] = pl;
    }
}

// ---------------------------------------------------------------------------
// bf16x3 tensor-core GEMM + fused al_s/al_d epilogue reduction.
// ---------------------------------------------------------------------------
#define GEMM_SMEM (16384 * 4)

__device__ __forceinline__ void mma_bf16(float* c, const uint32_t* a, const uint32_t* b) {
    asm volatile(
        "mma.sync.aligned.m16n8k16.row.col.f32.bf16.bf16.f32 "
        "{%0,%1,%2,%3}, {%4,%5,%6,%7}, {%8,%9}, {%0,%1,%2,%3};"
        : "+f"(c[0]), "+f"(c[1]), "+f"(c[2]), "+f"(c[3])
        : "r"(a[0]), "r"(a[1]), "r"(a[2]), "r"(a[3]), "r"(b[0]), "r"(b[1]));
}

__device__ __forceinline__ void cp16(uint32_t dst, const void* src) {
    asm volatile("cp.async.cg.shared.global [%0], [%1], 16;"
                 :: "r"(dst), "l"(src));
}

__global__ __launch_bounds__(256) void k_gemm_bf16(const uint32_t* __restrict__ Ahp,
                                                   const uint32_t* __restrict__ Alp,
                                                   const uint32_t* __restrict__ Bhp,
                                                   const uint32_t* __restrict__ Blp,
                                                   float* __restrict__ C,
                                                   const float* __restrict__ a_s,
                                                   const float* __restrict__ a_d,
                                                   float* __restrict__ als,
                                                   float* __restrict__ ald,
                                                   int Nrows, int K, int M,
                                                   int Cph, int H) {
    extern __shared__ uint32_t smem[];
    int tid = threadIdx.x;
    int lane = tid & 31, warp = tid >> 5;
    int g = lane >> 2, tg = lane & 3;
    int rowBase = blockIdx.x * 128;
    int colBase = blockIdx.y * 128;
    int warpM = (warp & 1) * 64;
    int warpN = (warp >> 1) * 32;
    int mbw = (warp & 1) * 4;
    int nbw = (warp >> 1) * 4;
    int KB16 = K >> 4;
    int NB = M >> 3;
    int mb0 = blockIdx.x * 8;
    int nb0 = blockIdx.y * 16;

    int ablk = tid >> 4;
    int akb  = ablk >> 3;
    int amb  = ablk & 7;
    int aj   = (tid & 15) * 8;
    size_t abase = (size_t)(mb0 + amb) * KB16 * 128 + aj;
    int bblk = tid >> 3;
    int bkb  = bblk >> 4;
    int bnb  = bblk & 15;
    int bj   = (tid & 7) * 8;
    size_t bbase = (size_t)(nb0 + bnb) * 64 + bj;

    uint32_t smemBase = (uint32_t)__cvta_generic_to_shared(smem);
    uint32_t AhD[2], AlD[2], BhD[2], BlD[2];
#pragma unroll
    for (int buf = 0; buf < 2; buf++) {
        AhD[buf] = smemBase + (buf * 2048 + tid * 8) * 4;
        AlD[buf] = smemBase + (4096 + buf * 2048 + tid * 8) * 4;
        BhD[buf] = smemBase + (8192 + buf * 2048 + tid * 8) * 4;
        BlD[buf] = smemBase + (12288 + buf * 2048 + tid * 8) * 4;
    }

    float acc[4][4][4];
#pragma unroll
    for (int mt = 0; mt < 4; mt++)
#pragma unroll
        for (int nt = 0; nt < 4; nt++)
#pragma unroll
            for (int i = 0; i < 4; i++) acc[mt][nt][i] = 0.f;

    const int NT = K >> 5;

    auto issue = [&](int t, int buf) {
        const uint32_t* ah = Ahp + abase + (size_t)(t * 2 + akb) * 128;
        const uint32_t* al = Alp + abase + (size_t)(t * 2 + akb) * 128;
        cp16(AhD[buf],      ah);
        cp16(AhD[buf] + 16, ah + 4);
        cp16(AlD[buf],      al);
        cp16(AlD[buf] + 16, al + 4);
        const uint32_t* bh = Bhp + (size_t)(t * 2 + bkb) * NB * 64 + bbase;
        const uint32_t* bl = Blp + (size_t)(t * 2 + bkb) * NB * 64 + bbase;
        cp16(BhD[buf],      bh);
        cp16(BhD[buf] + 16, bh + 4);
        cp16(BlD[buf],      bl);
        cp16(BlD[buf] + 16, bl + 4);
    };

    issue(0, 0);
    asm volatile("cp.async.commit_group;");

    for (int t = 0; t < NT; t++) {
        if (t + 1 < NT) issue(t + 1, (t + 1) & 1);
        asm volatile("cp.async.commit_group;");
        asm volatile("cp.async.wait_group 1;");
        __syncthreads();

        const uint32_t* As_h = smem + (t & 1) * 2048;
        const uint32_t* As_l = smem + 4096 + (t & 1) * 2048;
        const uint32_t* Bs_h = smem + 8192 + (t & 1) * 2048;
        const uint32_t* Bs_l = smem + 12288 + (t & 1) * 2048;

#pragma unroll
        for (int kk = 0; kk < 2; kk++) {
            uint4 ah4[4], al4[4];
#pragma unroll
            for (int mt = 0; mt < 4; mt++) {
                int bofs = (kk * 8 + mbw + mt) * 128 + lane * 4;
                ah4[mt] = *(const uint4*)&As_h[bofs];
                al4[mt] = *(const uint4*)&As_l[bofs];
            }
#pragma unroll
            for (int nt = 0; nt < 4; nt++) {
                int bofs = (kk * 16 + nbw + nt) * 64 + lane * 2;
                uint2 bh2 = *(const uint2*)&Bs_h[bofs];
                uint2 bl2 = *(const uint2*)&Bs_l[bofs];
                uint32_t bh[2] = {bh2.x, bh2.y};
                uint32_t bl[2] = {bl2.x, bl2.y};
#pragma unroll
                for (int mt = 0; mt < 4; mt++) {
                    mma_bf16(acc[mt][nt], (const uint32_t*)&ah4[mt], bh);
                    mma_bf16(acc[mt][nt], (const uint32_t*)&ah4[mt], bl);
                    mma_bf16(acc[mt][nt], (const uint32_t*)&al4[mt], bh);
                }
            }
        }
        __syncthreads();
    }

    // ---- store C + fused al reduction ----
    int head = (colBase + warpN) / Cph;
    float ps0[4] = {0, 0, 0, 0}, ps1[4] = {0, 0, 0, 0};
    float pd0[4] = {0, 0, 0, 0}, pd1[4] = {0, 0, 0, 0};

#pragma unroll
    for (int nt = 0; nt < 4; nt++) {
        int cc = colBase + warpN + nt * 8 + tg * 2;
        float s0 = a_s[cc], s1 = a_s[cc + 1];
        float d0 = a_d[cc], d1 = a_d[cc + 1];
#pragma unroll
        for (int mt = 0; mt < 4; mt++) {
            int r = rowBase + warpM + mt * 16 + g;
            if (r < Nrows)
                *(float2*)&C[(size_t)r * M + cc] = make_float2(acc[mt][nt][0], acc[mt][nt][1]);
            if (r + 8 < Nrows)
                *(float2*)&C[(size_t)(r + 8) * M + cc] = make_float2(acc[mt][nt][2], acc[mt][nt][3]);
            ps0[mt] += acc[mt][nt][0] * s0 + acc[mt][nt][1] * s1;
            ps1[mt] += acc[mt][nt][2] * s0 + acc[mt][nt][3] * s1;
            pd0[mt] += acc[mt][nt][0] * d0 + acc[mt][nt][1] * d1;
            pd1[mt] += acc[mt][nt][2] * d0 + acc[mt][nt][3] * d1;
        }
    }
#pragma unroll
    for (int mt = 0; mt < 4; mt++) {
        ps0[mt] += __shfl_xor_sync(0xFFFFFFFFu, ps0[mt], 1);
        ps0[mt] += __shfl_xor_sync(0xFFFFFFFFu, ps0[mt], 2);
        ps1[mt] += __shfl_xor_sync(0xFFFFFFFFu, ps1[mt], 1);
        ps1[mt] += __shfl_xor_sync(0xFFFFFFFFu, ps1[mt], 2);
        pd0[mt] += __shfl_xor_sync(0xFFFFFFFFu, pd0[mt], 1);
        pd0[mt] += __shfl_xor_sync(0xFFFFFFFFu, pd0[mt], 2);
        pd1[mt] += __shfl_xor_sync(0xFFFFFFFFu, pd1[mt], 1);
        pd1[mt] += __shfl_xor_sync(0xFFFFFFFFu, pd1[mt], 2);
    }
    if (tg == 0) {
#pragma unroll
        for (int mt = 0; mt < 4; mt++) {
            int r = rowBase + warpM + mt * 16 + g;
            if (r < Nrows) {
                atomicAdd(&als[r * H + head], ps0[mt]);
                atomicAdd(&ald[r * H + head], pd0[mt]);
            }
            if (r + 8 < Nrows) {
                atomicAdd(&als[(r + 8) * H + head], ps1[mt]);
                atomicAdd(&ald[(r + 8) * H + head], pd1[mt]);
            }
        }
    }
}

// ---------------------------------------------------------------------------
// Aggregation + fused streaming softmax: WARP per node.
// Lane owns cols 4*lane + 128*j (j < OUT/128); lane < H owns head stats.
// PACK=true: emit fragment-major bf16 hi/lo (KBLK kblocks).
// ---------------------------------------------------------------------------
template <int OUT, int H, int C, bool PACK, int KBLK>
__global__ void k_aggw(const float* __restrict__ h, const float* __restrict__ als,
                       const float* __restrict__ ald, const float* __restrict__ bias,
                       float* __restrict__ outF, uint32_t* __restrict__ outH,
                       uint32_t* __restrict__ outL) {
    constexpr int J = OUT / 128;
    int n = (blockIdx.x * blockDim.x + threadIdx.x) >> 5;
    if (n >= NN) return;
    int lane = threadIdx.x & 31;

    float ad = (lane < H) ? ald[n * H + lane] : 0.f;

    int s0 = g_off[n], s1 = g_off[n + 1];

    // phase A: streaming max + sum per head (lane < H)
    float m = -FLT_MAX, ssum = 0.f;
    for (int e = s0; e < s1; e++) {
        int src = g_srcS[e];
        if (lane < H) {
            float ev = als[src * H + lane] + ad;
            ev = fmaxf(ev, 0.2f * ev);
            if (ev > m) { ssum *= __expf(m - ev); m = ev; }
            ssum += __expf(ev - m);
        }
    }
    float dv = 1.f / (ssum + 1e-16f);

    int headOf[J];
#pragma unroll
    for (int j = 0; j < J; j++) headOf[j] = (4 * lane + 128 * j) / C;

    float4 acc[J];
#pragma unroll
    for (int j = 0; j < J; j++) acc[j] = make_float4(0.f, 0.f, 0.f, 0.f);

    // phase B: normalize + accumulate
    for (int e = s0; e < s1; e++) {
        int src = g_srcS[e];
        float av = 0.f;
        if (lane < H) {
            float ev = als[src * H + lane] + ad;
            ev = fmaxf(ev, 0.2f * ev);
            av = __expf(ev - m) * dv;
        }
        const float4* hp = (const float4*)(h + (size_t)src * OUT) + lane;
#pragma unroll
        for (int j = 0; j < J; j++) {
            float a = __shfl_sync(0xFFFFFFFFu, av, headOf[j]);
            float4 hv = hp[32 * j];
            acc[j].x += a * hv.x;
            acc[j].y += a * hv.y;
            acc[j].z += a * hv.z;
            acc[j].w += a * hv.w;
        }
    }

#pragma unroll
    for (int j = 0; j < J; j++) {
        int c0 = 4 * lane + 128 * j;
        float v0 = acc[j].x + bias[c0];
        float v1 = acc[j].y + bias[c0 + 1];
        float v2 = acc[j].z + bias[c0 + 2];
        float v3 = acc[j].w + bias[c0 + 3];
        v0 = (v0 > 0.f) ? v0 : 0.01f * v0;
        v1 = (v1 > 0.f) ? v1 : 0.01f * v1;
        v2 = (v2 > 0.f) ? v2 : 0.01f * v2;
        v3 = (v3 > 0.f) ? v3 : 0.01f * v3;
        if constexpr (PACK) {
            uint32_t ph0, pl0, ph1, pl1;
            split_pack(v0, v1, ph0, pl0);
            split_pack(v2, v3, ph1, pl1);
            int t0 = c0 >> 1;
            size_t i0 = a_frag_idx(n, t0, KBLK);
            size_t i1 = a_frag_idx(n, t0 + 1, KBLK);
            outH[i0] = ph0; outL[i0] = pl0;
            outH[i1] = ph1; outL[i1] = pl1;
        } else {
            *(float4*)&outF[(size_t)n * OUT + c0] = make_float4(v0, v1, v2, v3);
        }
    }
}

// ---------------------------------------------------------------------------
// Pooling + head
// ---------------------------------------------------------------------------
__device__ __forceinline__ int lower_bound_b(const int* __restrict__ b, int val) {
    int lo = 0, hi = NN;
    while (lo < hi) {
        int mid = (lo + hi) >> 1;
        if (ld_b(b, mid) < val) lo = mid + 1; else hi = mid;
    }
    return lo;
}

__global__ void k_poolseg(const int* __restrict__ batch, const float* __restrict__ o3,
                          const float* __restrict__ Wout, const float* __restrict__ bout,
                          float* __restrict__ out) {
    int gph = blockIdx.x, t = threadIdx.x;
    int lo = lower_bound_b(batch, gph);
    int hi = lower_bound_b(batch, gph + 1);
    float s = 0.f;
    for (int n = lo; n < hi; n++) s += o3[(size_t)n * 128 + t];
    float cnt = fmaxf((float)(hi - lo), 1.f);
    float v = (s / cnt) * Wout[t];
#pragma unroll
    for (int o = 16; o > 0; o >>= 1) v += __shfl_down_sync(0xFFFFFFFFu, v, o);
    __shared__ float red[4];
    if ((t & 31) == 0) red[t >> 5] = v;
    __syncthreads();
    if (t == 0) out[gph] = red[0] + red[1] + red[2] + red[3] + bout[0];
}

// ---------------------------------------------------------------------------
// Launch
// ---------------------------------------------------------------------------
extern "C" void kernel_launch(void* const* d_in, const int* in_sizes, int n_in,
                              void* d_out, int out_size) {
    int ix = 0, iei = 1, ib = 2, iW1 = 3, ia1s = 4, ia1d = 5, ib1 = 6,
        iW2 = 7, ia2s = 8, ia2d = 9, ib2 = 10, iW3 = 11, ia3s = 12,
        ia3d = 13, ib3 = 14, iWout = 15, ibout = 16;
    {
        int jx = -1, jei = -1, jb = -1, jW1 = -1, jW2 = -1, jW3 = -1, jbout = -1;
        int j1024[3], n1024 = 0;
        int j512[3],  n512 = 0;
        int j128[4],  n128 = 0;
        bool clean = true;
        for (int i = 0; i < n_in; i++) {
            int s = in_sizes[i];
            if      (s == 550000) { if (jx >= 0) clean = false; jx = i; }
            else if (s == 500000) { if (jei >= 0) clean = false; jei = i; }
            else if (s == 50000)  { if (jb >= 0) clean = false; jb = i; }
            else if (s == 11264)  { if (jW1 >= 0) clean = false; jW1 = i; }
            else if (s == 524288) { if (jW2 >= 0) clean = false; jW2 = i; }
            else if (s == 65536)  { if (jW3 >= 0) clean = false; jW3 = i; }
            else if (s == 1024)   { if (n1024 < 3) j1024[n1024] = i; n1024++; }
            else if (s == 512)    { if (n512  < 3) j512[n512]   = i; n512++; }
            else if (s == 128)    { if (n128  < 4) j128[n128]   = i; n128++; }
            else if (s == 1)      { if (jbout >= 0) clean = false; jbout = i; }
            else clean = false;
        }
        if (clean && jx >= 0 && jei >= 0 && jb >= 0 && jW1 >= 0 && jW2 >= 0 &&
            jW3 >= 0 && jbout >= 0 && n1024 == 3 && n512 == 3 && n128 == 4) {
            ix = jx; iei = jei; ib = jb; iW1 = jW1; iW2 = jW2; iW3 = jW3;
            ia1s = j1024[0]; ia1d = j1024[1]; ib1 = j1024[2];
            ia2s = j512[0];  ia2d = j512[1];  ib2 = j512[2];
            ia3s = j128[0];  ia3d = j128[1];  ib3 = j128[2]; iWout = j128[3];
            ibout = jbout;
        }
    }

    const float* x    = (const float*)d_in[ix];
    const int*   ei   = (const int*)d_in[iei];
    const int*   batch= (const int*)d_in[ib];
    const float* W1   = (const float*)d_in[iW1];
    const float* a1s  = (const float*)d_in[ia1s];
    const float* a1d  = (const float*)d_in[ia1d];
    const float* b1   = (const float*)d_in[ib1];
    const float* W2   = (const float*)d_in[iW2];
    const float* a2s  = (const float*)d_in[ia2s];
    const float* a2d  = (const float*)d_in[ia2d];
    const float* b2   = (const float*)d_in[ib2];
    const float* W3   = (const float*)d_in[iW3];
    const float* a3s  = (const float*)d_in[ia3s];
    const float* a3d  = (const float*)d_in[ia3d];
    const float* b3   = (const float*)d_in[ib3];
    const float* Wout = (const float*)d_in[iWout];
    const float* bout = (const float*)d_in[ibout];
    float* out = (float*)d_out;

    float* P = nullptr;      cudaGetSymbolAddress((void**)&P, g_P);
    uint32_t* Qh = nullptr;  cudaGetSymbolAddress((void**)&Qh, g_Qh);
    uint32_t* Ql = nullptr;  cudaGetSymbolAddress((void**)&Ql, g_Ql);
    uint32_t* B2h = nullptr; cudaGetSymbolAddress((void**)&B2h, g_B2h);
    uint32_t* B2l = nullptr; cudaGetSymbolAddress((void**)&B2l, g_B2l);
    uint32_t* B3h = nullptr; cudaGetSymbolAddress((void**)&B3h, g_B3h);
    uint32_t* B3l = nullptr; cudaGetSymbolAddress((void**)&B3l, g_B3l);
    float* als = nullptr;    cudaGetSymbolAddress((void**)&als, g_als);
    float* ald = nullptr;    cudaGetSymbolAddress((void**)&ald, g_ald);

    static bool attr_set = false;
    if (!attr_set) {
        cudaFuncSetAttribute(k_gemm_bf16, cudaFuncAttributeMaxDynamicSharedMemorySize,
                             GEMM_SMEM);
        attr_set = true;
    }

    // dtype detection + CSR build + weight prep (fragment-major)
    k_detect<<<1, 1024>>>(ei, batch);
    k_zero_deg<<<(NN + 255) / 256, 256>>>();
    k_count<<<(ET + 255) / 256, 256>>>(ei);
    k_wprep<<<(64 * 64 * 64 + 255) / 256, 256>>>(W2, B2h, B2l, 64, 512);
    k_wprep<<<(32 * 16 * 64 + 255) / 256, 256>>>(W3, B3h, B3l, 32, 128);
    k_scan1<<<50, 1024>>>();
    k_scan2<<<1, 32>>>();
    k_scan3<<<50, 1024>>>();
    k_scatter<<<(ET + 255) / 256, 256>>>(ei);

    // ---- Layer 1 (algebraic, fused softmax): o1 -> Qh/Ql fragment-major ----
    k_wsd<<<1, 128>>>(W1, a1s, a1d);
    k_alx<<<(NN + 255) / 256, 256>>>(x);
    k_aggx<<<(NN * 32 + 255) / 256, 256>>>(x);
    {
        dim3 grid((NN + 63) / 64, 8);
        k_proj<<<grid, 256>>>(W1, b1, Qh, Ql);
    }

    // ---- Layer 2: GEMM (+ fused al), fused-softmax agg ----
    cudaMemsetAsync(als, 0, NN * 8 * sizeof(float));
    cudaMemsetAsync(ald, 0, NN * 8 * sizeof(float));
    {
        dim3 grid((NN + 127) / 128, 4);
        k_gemm_bf16<<<grid, 256, GEMM_SMEM>>>(Qh, Ql, B2h, B2l, P,
                                              a2s, a2d, als, ald,
                                              NN, 1024, 512, 64, 8);
        k_aggw<512, 8, 64, true, 32><<<(NN * 32 + 255) / 256, 256>>>(
            P, als, ald, b2, nullptr, Qh, Ql);
    }

    // ---- Layer 3: GEMM (+ fused al), fused-softmax agg ----
    cudaMemsetAsync(als, 0, NN * 4 * sizeof(float));
    cudaMemsetAsync(ald, 0, NN * 4 * sizeof(float));
    {
        dim3 grid((NN + 127) / 128, 1);
        k_gemm_bf16<<<grid, 256, GEMM_SMEM>>>(Qh, Ql, B3h, B3l, P,
                                              a3s, a3d, als, ald,
                                              NN, 512, 128, 32, 4);
        k_aggw<128, 4, 32, false, 0><<<(NN * 32 + 255) / 256, 256>>>(
            P, als, ald, b3, (float*)Qh, nullptr, nullptr);
    }

    // ---- Pool + head ----
    k_poolseg<<<NG, 128>>>(batch, (float*)Qh, Wout, bout, out);
}

// round 15
// speedup vs baseline: 1.0283x; 1.0283x over previous
#include <cuda_runtime.h>
#include <cuda_bf16.h>
#include <float.h>
#include <stdint.h>

#define NN   50000
#define EE   250000
#define ET   300000
#define NG   64
#define MBPAD 3128   // ceil(50048/16): padded m16-block count (zero-init tail)

// ---------------------------------------------------------------------------
// Device scratch
// ---------------------------------------------------------------------------
__device__ __align__(16) float    g_P[(size_t)NN * 512];          // h2 / h3 (fp32)
__device__ __align__(16) uint32_t g_Qh[(size_t)MBPAD * 64 * 128]; // A frag hi / o3 fp32
__device__ __align__(16) uint32_t g_Ql[(size_t)MBPAD * 64 * 128]; // A frag lo
__device__ __align__(16) float    g_z[(size_t)NN * 88];

__device__ __align__(16) uint32_t g_B2h[64 * 64 * 64];   // W2 frag [kb][nb][64]
__device__ __align__(16) uint32_t g_B2l[64 * 64 * 64];
__device__ __align__(16) uint32_t g_B3h[32 * 16 * 64];
__device__ __align__(16) uint32_t g_B3l[32 * 16 * 64];

__device__ float g_als[NN * 8];
__device__ float g_ald[NN * 8];
__device__ float g_dinv[NN * 8];
__device__ float g_alpha[(size_t)ET * 8];
__device__ float g_ws[11 * 8];
__device__ float g_wd[11 * 8];

__device__ int   g_srcS[ET];
__device__ int   g_deg[NN];
__device__ int   g_off[NN + 1];
__device__ int   g_cur[NN];
__device__ int   g_bsum[64];
__device__ int   g_boff[64];

__device__ int g_ei64;
__device__ int g_b64;

__device__ __forceinline__ int clampN(int v) {
    return (v < 0) ? 0 : ((v >= NN) ? NN - 1 : v);
}

// bf16 hi/lo split of two adjacent-k values, packed (lo halfword = even k)
__device__ __forceinline__ void split_pack(float v0, float v1, uint32_t& ph, uint32_t& pl) {
    __nv_bfloat16 h0 = __float2bfloat16(v0);
    __nv_bfloat16 h1 = __float2bfloat16(v1);
    float r0 = v0 - __bfloat162float(h0);
    float r1 = v1 - __bfloat162float(h1);
    __nv_bfloat16 l0 = __float2bfloat16(r0);
    __nv_bfloat16 l1 = __float2bfloat16(r1);
    __nv_bfloat162 H = __halves2bfloat162(h0, h1);
    __nv_bfloat162 L = __halves2bfloat162(l0, l1);
    ph = *reinterpret_cast<uint32_t*>(&H);
    pl = *reinterpret_cast<uint32_t*>(&L);
}

// A fragment index: (n, c) -> u32 index in [mb][kb][128] frag array (KB16 kblocks)
__device__ __forceinline__ size_t a_frag_idx(int n, int c, int KB16) {
    int mb = n >> 4, rr = n & 15, kb = c >> 3, c8 = c & 7;
    int lane = (rr & 7) * 4 + (c8 & 3);
    int slot = (rr >> 3) + 2 * (c8 >> 2);
    return ((size_t)mb * KB16 + kb) * 128 + lane * 4 + slot;
}

// ---------------------------------------------------------------------------
// Parallel dtype detection
// ---------------------------------------------------------------------------
__global__ void k_detect(const int* __restrict__ ei, const int* __restrict__ batch) {
    int t = threadIdx.x;
    int ok1 = (ei[2 * t + 1] == 0);
    int idx = NN - 1024 + t;
    int ok2 = ((idx & 1) == 0) || (batch[idx] == 0);
    int a1 = __syncthreads_and(ok1);
    int a2 = __syncthreads_and(ok2);
    if (t == 0) { g_ei64 = a1; g_b64 = a2; }
}

__device__ __forceinline__ int ld_ei(const int* __restrict__ ei, int i) {
    return g_ei64 ? ei[2 * i] : ei[i];
}
__device__ __forceinline__ int ld_b(const int* __restrict__ b, int i) {
    return g_b64 ? b[2 * i] : b[i];
}

// ---------------------------------------------------------------------------
// CSR build
// ---------------------------------------------------------------------------
__global__ void k_zero_deg() {
    int i = blockIdx.x * blockDim.x + threadIdx.x;
    if (i < NN) g_deg[i] = 0;
}

__global__ void k_count(const int* __restrict__ ei) {
    int e = blockIdx.x * blockDim.x + threadIdx.x;
    if (e >= ET) return;
    int dst = (e < EE) ? clampN(ld_ei(ei, EE + e)) : (e - EE);
    atomicAdd(&g_deg[dst], 1);
}

__global__ void k_scan1() {
    int b = blockIdx.x, t = threadIdx.x;
    int i = b * 1000 + t;
    int v = (t < 1000 && i < NN) ? g_deg[i] : 0;
#pragma unroll
    for (int o = 16; o > 0; o >>= 1) v += __shfl_down_sync(0xFFFFFFFFu, v, o);
    __shared__ int w[32];
    int lane = t & 31, wid = t >> 5;
    if (lane == 0) w[wid] = v;
    __syncthreads();
    if (wid == 0) {
        int x = w[lane];
#pragma unroll
        for (int o = 16; o > 0; o >>= 1) x += __shfl_down_sync(0xFFFFFFFFu, x, o);
        if (lane == 0) g_bsum[b] = x;
    }
}

__global__ void k_scan2() {
    if (threadIdx.x != 0) return;
    int run = 0;
    for (int b = 0; b < 50; b++) { g_boff[b] = run; run += g_bsum[b]; }
    g_off[NN] = run;
}

__global__ void k_scan3() {
    int b = blockIdx.x, t = threadIdx.x;
    int i = b * 1000 + t;
    int v = (t < 1000 && i < NN) ? g_deg[i] : 0;
    int lane = t & 31, wid = t >> 5;
    int incl = v;
#pragma unroll
    for (int o = 1; o < 32; o <<= 1) {
        int u = __shfl_up_sync(0xFFFFFFFFu, incl, o);
        if (lane >= o) incl += u;
    }
    __shared__ int wl[32];
    if (lane == 31) wl[wid] = incl;
    __syncthreads();
    if (wid == 0) {
        int x = wl[lane];
#pragma unroll
        for (int o = 1; o < 32; o <<= 1) {
            int u = __shfl_up_sync(0xFFFFFFFFu, x, o);
            if (lane >= o) x += u;
        }
        wl[lane] = x;
    }
    __syncthreads();
    int excl = incl - v + ((wid > 0) ? wl[wid - 1] : 0);
    if (t < 1000 && i < NN) {
        int off = g_boff[b] + excl;
        g_off[i] = off;
        g_cur[i] = off;
    }
}

__global__ void k_scatter(const int* __restrict__ ei) {
    int e = blockIdx.x * blockDim.x + threadIdx.x;
    if (e >= ET) return;
    int src, dst;
    if (e < EE) { src = clampN(ld_ei(ei, e)); dst = clampN(ld_ei(ei, EE + e)); }
    else        { src = e - EE;               dst = e - EE; }
    int pos = atomicAdd(&g_cur[dst], 1);
    if (pos >= 0 && pos < ET) g_srcS[pos] = src;
}

// ---------------------------------------------------------------------------
// Weight prep: pack W (KxM fp32) into fragment-major hi/lo [kb][nb][64]
// ---------------------------------------------------------------------------
__global__ void k_wprep(const float* __restrict__ W, uint32_t* __restrict__ Bh,
                        uint32_t* __restrict__ Bl, int KB16, int M) {
    int idx = blockIdx.x * blockDim.x + threadIdx.x;
    int NB = M >> 3;
    if (idx >= KB16 * NB * 64) return;
    int block = idx >> 6, r = idx & 63;
    int lane = r >> 1, slot = r & 1;
    int kb = block / NB, nb = block - kb * NB;
    int coll = lane >> 2, tg = lane & 3;
    int c8 = tg + slot * 4;
    int k2 = kb * 8 + c8;
    int m = nb * 8 + coll;
    float a0 = W[(size_t)(2 * k2) * M + m];
    float a1 = W[(size_t)(2 * k2 + 1) * M + m];
    uint32_t ph, pl;
    split_pack(a0, a1, ph, pl);
    Bh[idx] = ph;
    Bl[idx] = pl;
}

// ---------------------------------------------------------------------------
// Layer-1 algebraic path
// ---------------------------------------------------------------------------
__global__ void k_wsd(const float* __restrict__ W1, const float* __restrict__ a1s,
                      const float* __restrict__ a1d) {
    int t = threadIdx.x;
    if (t >= 88) return;
    int k = t / 8, h = t % 8;
    float ss = 0.f, sd = 0.f;
    const float* wrow = W1 + k * 1024 + h * 128;
    const float* asr  = a1s + h * 128;
    const float* adr  = a1d + h * 128;
    for (int c = 0; c < 128; c++) {
        float w = wrow[c];
        ss += w * asr[c];
        sd += w * adr[c];
    }
    g_ws[k * 8 + h] = ss;
    g_wd[k * 8 + h] = sd;
}

__global__ void k_alx(const float* __restrict__ x) {
    __shared__ float ws[88], wd[88];
    int t = threadIdx.x;
    if (t < 88) { ws[t] = g_ws[t]; wd[t] = g_wd[t]; }
    __syncthreads();
    int n = blockIdx.x * blockDim.x + t;
    if (n >= NN) return;
    float xv[11];
#pragma unroll
    for (int k = 0; k < 11; k++) xv[k] = x[n * 11 + k];
#pragma unroll
    for (int h = 0; h < 8; h++) {
        float ps = 0.f, pd = 0.f;
#pragma unroll
        for (int k = 0; k < 11; k++) {
            ps += xv[k] * ws[k * 8 + h];
            pd += xv[k] * wd[k * 8 + h];
        }
        g_als[n * 8 + h] = ps;
        g_ald[n * 8 + h] = pd;
    }
}

// softmax stats: pass1 gathers e into alpha (then max), pass2 coalesced exp.
template <int H>
__global__ void k_stats(const float* __restrict__ als, const float* __restrict__ ald,
                        float* __restrict__ dinv, float* __restrict__ alpha) {
    int idx = blockIdx.x * blockDim.x + threadIdx.x;
    if (idx >= NN * H) return;
    int n = idx / H, hh = idx - n * H;
    float ad = ald[idx];
    int s0 = g_off[n], s1 = g_off[n + 1];
    float m = -FLT_MAX;
    for (int j = s0; j < s1; j++) {
        float e = als[g_srcS[j] * H + hh] + ad;
        e = fmaxf(e, 0.2f * e);
        alpha[(size_t)j * H + hh] = e;
        m = fmaxf(m, e);
    }
    float ssum = 0.f;
    for (int j = s0; j < s1; j++) {
        float ex = __expf(alpha[(size_t)j * H + hh] - m);
        alpha[(size_t)j * H + hh] = ex;
        ssum += ex;
    }
    dinv[idx] = 1.f / (ssum + 1e-16f);
}

// Layer-1 aggregation: warp per node
__global__ void k_aggx(const float* __restrict__ x) {
    int gw = (blockIdx.x * blockDim.x + threadIdx.x) >> 5;
    if (gw >= NN) return;
    int lane = threadIdx.x & 31;
    int n = gw;
    float dv = (lane < 8) ? g_dinv[n * 8 + lane] : 0.f;
    int i0 = lane, i1 = lane + 32, i2 = lane + 64;
    int h0 = i0 / 11, k0 = i0 - h0 * 11;
    int h1 = i1 / 11, k1 = i1 - h1 * 11;
    bool v2 = (i2 < 88);
    int h2 = v2 ? i2 / 11 : 0, k2 = v2 ? i2 - (i2 / 11) * 11 : 0;
    float z0 = 0.f, z1 = 0.f, z2 = 0.f;
    int s0 = g_off[n], s1 = g_off[n + 1];
    for (int j = s0; j < s1; j++) {
        int src = g_srcS[j];
        float xv = (lane < 11) ? x[src * 11 + lane] : 0.f;
        float av = (lane < 8) ? g_alpha[(size_t)j * 8 + lane] * dv : 0.f;
        float a0 = __shfl_sync(0xFFFFFFFFu, av, h0);
        float x0 = __shfl_sync(0xFFFFFFFFu, xv, k0);
        float a1 = __shfl_sync(0xFFFFFFFFu, av, h1);
        float x1 = __shfl_sync(0xFFFFFFFFu, xv, k1);
        float a2 = __shfl_sync(0xFFFFFFFFu, av, h2);
        float x2 = __shfl_sync(0xFFFFFFFFu, xv, k2);
        z0 += a0 * x0;
        z1 += a1 * x1;
        if (v2) z2 += a2 * x2;
    }
    g_z[(size_t)n * 88 + i0] = z0;
    g_z[(size_t)n * 88 + i1] = z1;
    if (v2) g_z[(size_t)n * 88 + i2] = z2;
}

// o1 projection; emits fragment-major bf16 hi/lo (A of GEMM2, KB16=64)
__global__ __launch_bounds__(256) void k_proj(const float* __restrict__ W1,
                                              const float* __restrict__ b1,
                                              uint32_t* __restrict__ oh,
                                              uint32_t* __restrict__ ol) {
    __shared__ float Wh[11][128];
    __shared__ float zt[64][11];
    int n0 = blockIdx.x * 64;
    int h = blockIdx.y;
    int t = threadIdx.x;
    for (int i = t; i < 11 * 128; i += 256) {
        int k = i >> 7, c = i & 127;
        Wh[k][c] = W1[k * 1024 + h * 128 + c];
    }
    for (int i = t; i < 64 * 11; i += 256) {
        int r = i / 11, k = i - r * 11;
        int n = n0 + r;
        zt[r][k] = (n < NN) ? g_z[(size_t)n * 88 + h * 11 + k] : 0.f;
    }
    __syncthreads();
    int c = t & 63;
    int rg = t >> 6;
    float bias0 = b1[h * 128 + 2 * c];
    float bias1 = b1[h * 128 + 2 * c + 1];
    int cg = h * 64 + c;
#pragma unroll 4
    for (int i = 0; i < 16; i++) {
        int r = rg * 16 + i;
        int n = n0 + r;
        if (n >= NN) break;
        float a0 = bias0, a1 = bias1;
#pragma unroll
        for (int k = 0; k < 11; k++) {
            float zz = zt[r][k];
            a0 += zz * Wh[k][2 * c];
            a1 += zz * Wh[k][2 * c + 1];
        }
        a0 = (a0 > 0.f) ? a0 : 0.01f * a0;
        a1 = (a1 > 0.f) ? a1 : 0.01f * a1;
        uint32_t ph, pl;
        split_pack(a0, a1, ph, pl);
        size_t idx = a_frag_idx(n, cg, 64);
        oh[idx] = ph;
        ol[idx] = pl;
    }
}

// ---------------------------------------------------------------------------
// bf16x3 tensor-core GEMM + fused al_s/al_d epilogue reduction.
// ---------------------------------------------------------------------------
#define GEMM_SMEM (16384 * 4)

__device__ __forceinline__ void mma_bf16(float* c, const uint32_t* a, const uint32_t* b) {
    asm volatile(
        "mma.sync.aligned.m16n8k16.row.col.f32.bf16.bf16.f32 "
        "{%0,%1,%2,%3}, {%4,%5,%6,%7}, {%8,%9}, {%0,%1,%2,%3};"
        : "+f"(c[0]), "+f"(c[1]), "+f"(c[2]), "+f"(c[3])
        : "r"(a[0]), "r"(a[1]), "r"(a[2]), "r"(a[3]), "r"(b[0]), "r"(b[1]));
}

__device__ __forceinline__ void cp16(uint32_t dst, const void* src) {
    asm volatile("cp.async.cg.shared.global [%0], [%1], 16;"
                 :: "r"(dst), "l"(src));
}

__global__ __launch_bounds__(256) void k_gemm_bf16(const uint32_t* __restrict__ Ahp,
                                                   const uint32_t* __restrict__ Alp,
                                                   const uint32_t* __restrict__ Bhp,
                                                   const uint32_t* __restrict__ Blp,
                                                   float* __restrict__ C,
                                                   const float* __restrict__ a_s,
                                                   const float* __restrict__ a_d,
                                                   float* __restrict__ als,
                                                   float* __restrict__ ald,
                                                   int Nrows, int K, int M,
                                                   int Cph, int H) {
    extern __shared__ uint32_t smem[];
    int tid = threadIdx.x;
    int lane = tid & 31, warp = tid >> 5;
    int g = lane >> 2, tg = lane & 3;
    int rowBase = blockIdx.x * 128;
    int colBase = blockIdx.y * 128;
    int warpM = (warp & 1) * 64;
    int warpN = (warp >> 1) * 32;
    int mbw = (warp & 1) * 4;
    int nbw = (warp >> 1) * 4;
    int KB16 = K >> 4;
    int NB = M >> 3;
    int mb0 = blockIdx.x * 8;
    int nb0 = blockIdx.y * 16;

    int ablk = tid >> 4;
    int akb  = ablk >> 3;
    int amb  = ablk & 7;
    int aj   = (tid & 15) * 8;
    size_t abase = (size_t)(mb0 + amb) * KB16 * 128 + aj;
    int bblk = tid >> 3;
    int bkb  = bblk >> 4;
    int bnb  = bblk & 15;
    int bj   = (tid & 7) * 8;
    size_t bbase = (size_t)(nb0 + bnb) * 64 + bj;

    uint32_t smemBase = (uint32_t)__cvta_generic_to_shared(smem);
    uint32_t AhD[2], AlD[2], BhD[2], BlD[2];
#pragma unroll
    for (int buf = 0; buf < 2; buf++) {
        AhD[buf] = smemBase + (buf * 2048 + tid * 8) * 4;
        AlD[buf] = smemBase + (4096 + buf * 2048 + tid * 8) * 4;
        BhD[buf] = smemBase + (8192 + buf * 2048 + tid * 8) * 4;
        BlD[buf] = smemBase + (12288 + buf * 2048 + tid * 8) * 4;
    }

    float acc[4][4][4];
#pragma unroll
    for (int mt = 0; mt < 4; mt++)
#pragma unroll
        for (int nt = 0; nt < 4; nt++)
#pragma unroll
            for (int i = 0; i < 4; i++) acc[mt][nt][i] = 0.f;

    const int NT = K >> 5;

    auto issue = [&](int t, int buf) {
        const uint32_t* ah = Ahp + abase + (size_t)(t * 2 + akb) * 128;
        const uint32_t* al = Alp + abase + (size_t)(t * 2 + akb) * 128;
        cp16(AhD[buf],      ah);
        cp16(AhD[buf] + 16, ah + 4);
        cp16(AlD[buf],      al);
        cp16(AlD[buf] + 16, al + 4);
        const uint32_t* bh = Bhp + (size_t)(t * 2 + bkb) * NB * 64 + bbase;
        const uint32_t* bl = Blp + (size_t)(t * 2 + bkb) * NB * 64 + bbase;
        cp16(BhD[buf],      bh);
        cp16(BhD[buf] + 16, bh + 4);
        cp16(BlD[buf],      bl);
        cp16(BlD[buf] + 16, bl + 4);
    };

    issue(0, 0);
    asm volatile("cp.async.commit_group;");

    for (int t = 0; t < NT; t++) {
        if (t + 1 < NT) issue(t + 1, (t + 1) & 1);
        asm volatile("cp.async.commit_group;");
        asm volatile("cp.async.wait_group 1;");
        __syncthreads();

        const uint32_t* As_h = smem + (t & 1) * 2048;
        const uint32_t* As_l = smem + 4096 + (t & 1) * 2048;
        const uint32_t* Bs_h = smem + 8192 + (t & 1) * 2048;
        const uint32_t* Bs_l = smem + 12288 + (t & 1) * 2048;

#pragma unroll
        for (int kk = 0; kk < 2; kk++) {
            uint4 ah4[4], al4[4];
#pragma unroll
            for (int mt = 0; mt < 4; mt++) {
                int bofs = (kk * 8 + mbw + mt) * 128 + lane * 4;
                ah4[mt] = *(const uint4*)&As_h[bofs];
                al4[mt] = *(const uint4*)&As_l[bofs];
            }
#pragma unroll
            for (int nt = 0; nt < 4; nt++) {
                int bofs = (kk * 16 + nbw + nt) * 64 + lane * 2;
                uint2 bh2 = *(const uint2*)&Bs_h[bofs];
                uint2 bl2 = *(const uint2*)&Bs_l[bofs];
                uint32_t bh[2] = {bh2.x, bh2.y};
                uint32_t bl[2] = {bl2.x, bl2.y};
#pragma unroll
                for (int mt = 0; mt < 4; mt++) {
                    mma_bf16(acc[mt][nt], (const uint32_t*)&ah4[mt], bh);
                    mma_bf16(acc[mt][nt], (const uint32_t*)&ah4[mt], bl);
                    mma_bf16(acc[mt][nt], (const uint32_t*)&al4[mt], bh);
                }
            }
        }
        __syncthreads();
    }

    // ---- store C + fused al reduction ----
    int head = (colBase + warpN) / Cph;
    float ps0[4] = {0, 0, 0, 0}, ps1[4] = {0, 0, 0, 0};
    float pd0[4] = {0, 0, 0, 0}, pd1[4] = {0, 0, 0, 0};

#pragma unroll
    for (int nt = 0; nt < 4; nt++) {
        int cc = colBase + warpN + nt * 8 + tg * 2;
        float s0 = a_s[cc], s1 = a_s[cc + 1];
        float d0 = a_d[cc], d1 = a_d[cc + 1];
#pragma unroll
        for (int mt = 0; mt < 4; mt++) {
            int r = rowBase + warpM + mt * 16 + g;
            if (r < Nrows)
                *(float2*)&C[(size_t)r * M + cc] = make_float2(acc[mt][nt][0], acc[mt][nt][1]);
            if (r + 8 < Nrows)
                *(float2*)&C[(size_t)(r + 8) * M + cc] = make_float2(acc[mt][nt][2], acc[mt][nt][3]);
            ps0[mt] += acc[mt][nt][0] * s0 + acc[mt][nt][1] * s1;
            ps1[mt] += acc[mt][nt][2] * s0 + acc[mt][nt][3] * s1;
            pd0[mt] += acc[mt][nt][0] * d0 + acc[mt][nt][1] * d1;
            pd1[mt] += acc[mt][nt][2] * d0 + acc[mt][nt][3] * d1;
        }
    }
#pragma unroll
    for (int mt = 0; mt < 4; mt++) {
        ps0[mt] += __shfl_xor_sync(0xFFFFFFFFu, ps0[mt], 1);
        ps0[mt] += __shfl_xor_sync(0xFFFFFFFFu, ps0[mt], 2);
        ps1[mt] += __shfl_xor_sync(0xFFFFFFFFu, ps1[mt], 1);
        ps1[mt] += __shfl_xor_sync(0xFFFFFFFFu, ps1[mt], 2);
        pd0[mt] += __shfl_xor_sync(0xFFFFFFFFu, pd0[mt], 1);
        pd0[mt] += __shfl_xor_sync(0xFFFFFFFFu, pd0[mt], 2);
        pd1[mt] += __shfl_xor_sync(0xFFFFFFFFu, pd1[mt], 1);
        pd1[mt] += __shfl_xor_sync(0xFFFFFFFFu, pd1[mt], 2);
    }
    if (tg == 0) {
#pragma unroll
        for (int mt = 0; mt < 4; mt++) {
            int r = rowBase + warpM + mt * 16 + g;
            if (r < Nrows) {
                atomicAdd(&als[r * H + head], ps0[mt]);
                atomicAdd(&ald[r * H + head], pd0[mt]);
            }
            if (r + 8 < Nrows) {
                atomicAdd(&als[(r + 8) * H + head], ps1[mt]);
                atomicAdd(&ald[(r + 8) * H + head], pd1[mt]);
            }
        }
    }
}

// ---------------------------------------------------------------------------
// Aggregation: WARP per node, chunked operand prefetch.
// Lane owns cols 4*lane + 128*j. Per chunk of EC=32/H edges: src via lanes
// 0..cnt, alpha via one coalesced 128B line (lane = eoff*H + hh).
// PACK=true: emit fragment-major bf16 hi/lo (KBLK kblocks).
// ---------------------------------------------------------------------------
template <int OUT, int H, int C, bool PACK, int KBLK>
__global__ void k_aggw(const float* __restrict__ h, const float* __restrict__ alpha,
                       const float* __restrict__ dinv, const float* __restrict__ bias,
                       float* __restrict__ outF, uint32_t* __restrict__ outH,
                       uint32_t* __restrict__ outL) {
    constexpr int J = OUT / 128;
    constexpr int EC = 32 / H;     // edges per chunk (4 or 8)
    int n = (blockIdx.x * blockDim.x + threadIdx.x) >> 5;
    if (n >= NN) return;
    int lane = threadIdx.x & 31;

    float dv = (lane < H) ? dinv[n * H + lane] : 0.f;
    int hh = lane & (H - 1);       // lane's head in chunk layout
    int eoff = lane / H;           // lane's edge offset in chunk
    float dvh = __shfl_sync(0xFFFFFFFFu, dv, hh);

    int headOf[J];
#pragma unroll
    for (int j = 0; j < J; j++) headOf[j] = (4 * lane + 128 * j) / C;

    float4 acc[J];
#pragma unroll
    for (int j = 0; j < J; j++) acc[j] = make_float4(0.f, 0.f, 0.f, 0.f);

    int s0 = g_off[n], s1 = g_off[n + 1];
    for (int e0 = s0; e0 < s1; e0 += EC) {
        int cnt = min(EC, s1 - e0);
        int srcl = (lane < cnt) ? g_srcS[e0 + lane] : 0;
        // coalesced alpha chunk: index (e0+eoff)*H + hh == e0*H + lane
        float av = (eoff < cnt) ? alpha[(size_t)e0 * H + lane] * dvh : 0.f;
        for (int i = 0; i < cnt; i++) {
            int src = __shfl_sync(0xFFFFFFFFu, srcl, i);
            const float4* hp = (const float4*)(h + (size_t)src * OUT) + lane;
#pragma unroll
            for (int j = 0; j < J; j++) {
                float a = __shfl_sync(0xFFFFFFFFu, av, i * H + headOf[j]);
                float4 hv = hp[32 * j];
                acc[j].x += a * hv.x;
                acc[j].y += a * hv.y;
                acc[j].z += a * hv.z;
                acc[j].w += a * hv.w;
            }
        }
    }

#pragma unroll
    for (int j = 0; j < J; j++) {
        int c0 = 4 * lane + 128 * j;
        float v0 = acc[j].x + bias[c0];
        float v1 = acc[j].y + bias[c0 + 1];
        float v2 = acc[j].z + bias[c0 + 2];
        float v3 = acc[j].w + bias[c0 + 3];
        v0 = (v0 > 0.f) ? v0 : 0.01f * v0;
        v1 = (v1 > 0.f) ? v1 : 0.01f * v1;
        v2 = (v2 > 0.f) ? v2 : 0.01f * v2;
        v3 = (v3 > 0.f) ? v3 : 0.01f * v3;
        if constexpr (PACK) {
            uint32_t ph0, pl0, ph1, pl1;
            split_pack(v0, v1, ph0, pl0);
            split_pack(v2, v3, ph1, pl1);
            int t0 = c0 >> 1;
            size_t i0 = a_frag_idx(n, t0, KBLK);
            size_t i1 = a_frag_idx(n, t0 + 1, KBLK);
            outH[i0] = ph0; outL[i0] = pl0;
            outH[i1] = ph1; outL[i1] = pl1;
        } else {
            *(float4*)&outF[(size_t)n * OUT + c0] = make_float4(v0, v1, v2, v3);
        }
    }
}

// ---------------------------------------------------------------------------
// Pooling + head
// ---------------------------------------------------------------------------
__device__ __forceinline__ int lower_bound_b(const int* __restrict__ b, int val) {
    int lo = 0, hi = NN;
    while (lo < hi) {
        int mid = (lo + hi) >> 1;
        if (ld_b(b, mid) < val) lo = mid + 1; else hi = mid;
    }
    return lo;
}

__global__ void k_poolseg(const int* __restrict__ batch, const float* __restrict__ o3,
                          const float* __restrict__ Wout, const float* __restrict__ bout,
                          float* __restrict__ out) {
    int gph = blockIdx.x, t = threadIdx.x;
    int lo = lower_bound_b(batch, gph);
    int hi = lower_bound_b(batch, gph + 1);
    float s = 0.f;
    for (int n = lo; n < hi; n++) s += o3[(size_t)n * 128 + t];
    float cnt = fmaxf((float)(hi - lo), 1.f);
    float v = (s / cnt) * Wout[t];
#pragma unroll
    for (int o = 16; o > 0; o >>= 1) v += __shfl_down_sync(0xFFFFFFFFu, v, o);
    __shared__ float red[4];
    if ((t & 31) == 0) red[t >> 5] = v;
    __syncthreads();
    if (t == 0) out[gph] = red[0] + red[1] + red[2] + red[3] + bout[0];
}

// ---------------------------------------------------------------------------
// Launch
// ---------------------------------------------------------------------------
extern "C" void kernel_launch(void* const* d_in, const int* in_sizes, int n_in,
                              void* d_out, int out_size) {
    int ix = 0, iei = 1, ib = 2, iW1 = 3, ia1s = 4, ia1d = 5, ib1 = 6,
        iW2 = 7, ia2s = 8, ia2d = 9, ib2 = 10, iW3 = 11, ia3s = 12,
        ia3d = 13, ib3 = 14, iWout = 15, ibout = 16;
    {
        int jx = -1, jei = -1, jb = -1, jW1 = -1, jW2 = -1, jW3 = -1, jbout = -1;
        int j1024[3], n1024 = 0;
        int j512[3],  n512 = 0;
        int j128[4],  n128 = 0;
        bool clean = true;
        for (int i = 0; i < n_in; i++) {
            int s = in_sizes[i];
            if      (s == 550000) { if (jx >= 0) clean = false; jx = i; }
            else if (s == 500000) { if (jei >= 0) clean = false; jei = i; }
            else if (s == 50000)  { if (jb >= 0) clean = false; jb = i; }
            else if (s == 11264)  { if (jW1 >= 0) clean = false; jW1 = i; }
            else if (s == 524288) { if (jW2 >= 0) clean = false; jW2 = i; }
            else if (s == 65536)  { if (jW3 >= 0) clean = false; jW3 = i; }
            else if (s == 1024)   { if (n1024 < 3) j1024[n1024] = i; n1024++; }
            else if (s == 512)    { if (n512  < 3) j512[n512]   = i; n512++; }
            else if (s == 128)    { if (n128  < 4) j128[n128]   = i; n128++; }
            else if (s == 1)      { if (jbout >= 0) clean = false; jbout = i; }
            else clean = false;
        }
        if (clean && jx >= 0 && jei >= 0 && jb >= 0 && jW1 >= 0 && jW2 >= 0 &&
            jW3 >= 0 && jbout >= 0 && n1024 == 3 && n512 == 3 && n128 == 4) {
            ix = jx; iei = jei; ib = jb; iW1 = jW1; iW2 = jW2; iW3 = jW3;
            ia1s = j1024[0]; ia1d = j1024[1]; ib1 = j1024[2];
            ia2s = j512[0];  ia2d = j512[1];  ib2 = j512[2];
            ia3s = j128[0];  ia3d = j128[1];  ib3 = j128[2]; iWout = j128[3];
            ibout = jbout;
        }
    }

    const float* x    = (const float*)d_in[ix];
    const int*   ei   = (const int*)d_in[iei];
    const int*   batch= (const int*)d_in[ib];
    const float* W1   = (const float*)d_in[iW1];
    const float* a1s  = (const float*)d_in[ia1s];
    const float* a1d  = (const float*)d_in[ia1d];
    const float* b1   = (const float*)d_in[ib1];
    const float* W2   = (const float*)d_in[iW2];
    const float* a2s  = (const float*)d_in[ia2s];
    const float* a2d  = (const float*)d_in[ia2d];
    const float* b2   = (const float*)d_in[ib2];
    const float* W3   = (const float*)d_in[iW3];
    const float* a3s  = (const float*)d_in[ia3s];
    const float* a3d  = (const float*)d_in[ia3d];
    const float* b3   = (const float*)d_in[ib3];
    const float* Wout = (const float*)d_in[iWout];
    const float* bout = (const float*)d_in[ibout];
    float* out = (float*)d_out;

    float* P = nullptr;      cudaGetSymbolAddress((void**)&P, g_P);
    uint32_t* Qh = nullptr;  cudaGetSymbolAddress((void**)&Qh, g_Qh);
    uint32_t* Ql = nullptr;  cudaGetSymbolAddress((void**)&Ql, g_Ql);
    uint32_t* B2h = nullptr; cudaGetSymbolAddress((void**)&B2h, g_B2h);
    uint32_t* B2l = nullptr; cudaGetSymbolAddress((void**)&B2l, g_B2l);
    uint32_t* B3h = nullptr; cudaGetSymbolAddress((void**)&B3h, g_B3h);
    uint32_t* B3l = nullptr; cudaGetSymbolAddress((void**)&B3l, g_B3l);
    float* als = nullptr;    cudaGetSymbolAddress((void**)&als, g_als);
    float* ald = nullptr;    cudaGetSymbolAddress((void**)&ald, g_ald);
    float* dinv = nullptr;   cudaGetSymbolAddress((void**)&dinv, g_dinv);
    float* alpha = nullptr;  cudaGetSymbolAddress((void**)&alpha, g_alpha);

    static bool attr_set = false;
    if (!attr_set) {
        cudaFuncSetAttribute(k_gemm_bf16, cudaFuncAttributeMaxDynamicSharedMemorySize,
                             GEMM_SMEM);
        attr_set = true;
    }

    // dtype detection + CSR build + weight prep (fragment-major)
    k_detect<<<1, 1024>>>(ei, batch);
    k_zero_deg<<<(NN + 255) / 256, 256>>>();
    k_count<<<(ET + 255) / 256, 256>>>(ei);
    k_wprep<<<(64 * 64 * 64 + 255) / 256, 256>>>(W2, B2h, B2l, 64, 512);
    k_wprep<<<(32 * 16 * 64 + 255) / 256, 256>>>(W3, B3h, B3l, 32, 128);
    k_scan1<<<50, 1024>>>();
    k_scan2<<<1, 32>>>();
    k_scan3<<<50, 1024>>>();
    k_scatter<<<(ET + 255) / 256, 256>>>(ei);

    // ---- Layer 1 (algebraic): o1 -> Qh/Ql fragment-major ----
    k_wsd<<<1, 128>>>(W1, a1s, a1d);
    k_alx<<<(NN + 255) / 256, 256>>>(x);
    k_stats<8><<<(NN * 8 + 255) / 256, 256>>>(als, ald, dinv, alpha);
    k_aggx<<<(NN * 32 + 255) / 256, 256>>>(x);
    {
        dim3 grid((NN + 63) / 64, 8);
        k_proj<<<grid, 256>>>(W1, b1, Qh, Ql);
    }

    // ---- Layer 2: GEMM (+ fused al), stats, agg (warp-per-node, prefetch) ----
    cudaMemsetAsync(als, 0, NN * 8 * sizeof(float));
    cudaMemsetAsync(ald, 0, NN * 8 * sizeof(float));
    {
        dim3 grid((NN + 127) / 128, 4);
        k_gemm_bf16<<<grid, 256, GEMM_SMEM>>>(Qh, Ql, B2h, B2l, P,
                                              a2s, a2d, als, ald,
                                              NN, 1024, 512, 64, 8);
        k_stats<8><<<(NN * 8 + 255) / 256, 256>>>(als, ald, dinv, alpha);
        k_aggw<512, 8, 64, true, 32><<<(NN * 32 + 255) / 256, 256>>>(
            P, alpha, dinv, b2, nullptr, Qh, Ql);
    }

    // ---- Layer 3: GEMM (+ fused al), stats, agg (warp-per-node, prefetch) ----
    cudaMemsetAsync(als, 0, NN * 4 * sizeof(float));
    cudaMemsetAsync(ald, 0, NN * 4 * sizeof(float));
    {
        dim3 grid((NN + 127) / 128, 1);
        k_gemm_bf16<<<grid, 256, GEMM_SMEM>>>(Qh, Ql, B3h, B3l, P,
                                              a3s, a3d, als, ald,
                                              NN, 512, 128, 32, 4);
        k_stats<4><<<(NN * 4 + 255) / 256, 256>>>(als, ald, dinv, alpha);
        k_aggw<128, 4, 32, false, 0><<<(NN * 32 + 255) / 256, 256>>>(
            P, alpha, dinv, b3, (float*)Qh, nullptr, nullptr);
    }

    // ---- Pool + head ----
    k_poolseg<<<NG, 128>>>(batch, (float*)Qh, Wout, bout, out);
}

// round 16
// speedup vs baseline: 1.0347x; 1.0062x over previous
#include <cuda_runtime.h>
#include <cuda_bf16.h>
#include <float.h>
#include <stdint.h>

#define NN   50000
#define EE   250000
#define ET   300000
#define NG   64
#define MBPAD 3128   // ceil(50048/16): padded m16-block count (zero-init tail)

// ---------------------------------------------------------------------------
// Device scratch
// ---------------------------------------------------------------------------
__device__ __align__(16) float    g_P[(size_t)NN * 512];          // h2 / h3 (fp32)
__device__ __align__(16) uint32_t g_Qh[(size_t)MBPAD * 64 * 128]; // A frag hi / o3 fp32
__device__ __align__(16) uint32_t g_Ql[(size_t)MBPAD * 64 * 128]; // A frag lo
__device__ __align__(16) float    g_z[(size_t)NN * 88];

__device__ __align__(16) uint32_t g_B2h[64 * 64 * 64];   // W2 frag [kb][nb][64]
__device__ __align__(16) uint32_t g_B2l[64 * 64 * 64];
__device__ __align__(16) uint32_t g_B3h[32 * 16 * 64];
__device__ __align__(16) uint32_t g_B3l[32 * 16 * 64];

__device__ float g_als[NN * 8];
__device__ float g_ald[NN * 8];
__device__ float g_dinv[NN * 8];
__device__ float g_alpha[(size_t)ET * 8];
__device__ float g_ws[11 * 8];
__device__ float g_wd[11 * 8];

__device__ int   g_srcS[ET];
__device__ int   g_deg[NN];
__device__ int   g_off[NN + 1];
__device__ int   g_cur[NN];
__device__ int   g_bsum[64];
__device__ int   g_boff[64];

__device__ int g_ei64;
__device__ int g_b64;

__device__ __forceinline__ int clampN(int v) {
    return (v < 0) ? 0 : ((v >= NN) ? NN - 1 : v);
}

// bf16 hi/lo split of two adjacent-k values, packed (lo halfword = even k)
__device__ __forceinline__ void split_pack(float v0, float v1, uint32_t& ph, uint32_t& pl) {
    __nv_bfloat16 h0 = __float2bfloat16(v0);
    __nv_bfloat16 h1 = __float2bfloat16(v1);
    float r0 = v0 - __bfloat162float(h0);
    float r1 = v1 - __bfloat162float(h1);
    __nv_bfloat16 l0 = __float2bfloat16(r0);
    __nv_bfloat16 l1 = __float2bfloat16(r1);
    __nv_bfloat162 H = __halves2bfloat162(h0, h1);
    __nv_bfloat162 L = __halves2bfloat162(l0, l1);
    ph = *reinterpret_cast<uint32_t*>(&H);
    pl = *reinterpret_cast<uint32_t*>(&L);
}

// A fragment index: (n, c) -> u32 index in [mb][kb][128] frag array (KB16 kblocks)
__device__ __forceinline__ size_t a_frag_idx(int n, int c, int KB16) {
    int mb = n >> 4, rr = n & 15, kb = c >> 3, c8 = c & 7;
    int lane = (rr & 7) * 4 + (c8 & 3);
    int slot = (rr >> 3) + 2 * (c8 >> 2);
    return ((size_t)mb * KB16 + kb) * 128 + lane * 4 + slot;
}

// ---------------------------------------------------------------------------
// Parallel dtype detection
// ---------------------------------------------------------------------------
__global__ void k_detect(const int* __restrict__ ei, const int* __restrict__ batch) {
    int t = threadIdx.x;
    int ok1 = (ei[2 * t + 1] == 0);
    int idx = NN - 1024 + t;
    int ok2 = ((idx & 1) == 0) || (batch[idx] == 0);
    int a1 = __syncthreads_and(ok1);
    int a2 = __syncthreads_and(ok2);
    if (t == 0) { g_ei64 = a1; g_b64 = a2; }
}

__device__ __forceinline__ int ld_ei(const int* __restrict__ ei, int i) {
    return g_ei64 ? ei[2 * i] : ei[i];
}
__device__ __forceinline__ int ld_b(const int* __restrict__ b, int i) {
    return g_b64 ? b[2 * i] : b[i];
}

// ---------------------------------------------------------------------------
// CSR build
// ---------------------------------------------------------------------------
__global__ void k_zero_deg() {
    int i = blockIdx.x * blockDim.x + threadIdx.x;
    if (i < NN) g_deg[i] = 0;
}

__global__ void k_count(const int* __restrict__ ei) {
    int e = blockIdx.x * blockDim.x + threadIdx.x;
    if (e >= ET) return;
    int dst = (e < EE) ? clampN(ld_ei(ei, EE + e)) : (e - EE);
    atomicAdd(&g_deg[dst], 1);
}

__global__ void k_scan1() {
    int b = blockIdx.x, t = threadIdx.x;
    int i = b * 1000 + t;
    int v = (t < 1000 && i < NN) ? g_deg[i] : 0;
#pragma unroll
    for (int o = 16; o > 0; o >>= 1) v += __shfl_down_sync(0xFFFFFFFFu, v, o);
    __shared__ int w[32];
    int lane = t & 31, wid = t >> 5;
    if (lane == 0) w[wid] = v;
    __syncthreads();
    if (wid == 0) {
        int x = w[lane];
#pragma unroll
        for (int o = 16; o > 0; o >>= 1) x += __shfl_down_sync(0xFFFFFFFFu, x, o);
        if (lane == 0) g_bsum[b] = x;
    }
}

__global__ void k_scan2() {
    if (threadIdx.x != 0) return;
    int run = 0;
    for (int b = 0; b < 50; b++) { g_boff[b] = run; run += g_bsum[b]; }
    g_off[NN] = run;
}

__global__ void k_scan3() {
    int b = blockIdx.x, t = threadIdx.x;
    int i = b * 1000 + t;
    int v = (t < 1000 && i < NN) ? g_deg[i] : 0;
    int lane = t & 31, wid = t >> 5;
    int incl = v;
#pragma unroll
    for (int o = 1; o < 32; o <<= 1) {
        int u = __shfl_up_sync(0xFFFFFFFFu, incl, o);
        if (lane >= o) incl += u;
    }
    __shared__ int wl[32];
    if (lane == 31) wl[wid] = incl;
    __syncthreads();
    if (wid == 0) {
        int x = wl[lane];
#pragma unroll
        for (int o = 1; o < 32; o <<= 1) {
            int u = __shfl_up_sync(0xFFFFFFFFu, x, o);
            if (lane >= o) x += u;
        }
        wl[lane] = x;
    }
    __syncthreads();
    int excl = incl - v + ((wid > 0) ? wl[wid - 1] : 0);
    if (t < 1000 && i < NN) {
        int off = g_boff[b] + excl;
        g_off[i] = off;
        g_cur[i] = off;
    }
}

__global__ void k_scatter(const int* __restrict__ ei) {
    int e = blockIdx.x * blockDim.x + threadIdx.x;
    if (e >= ET) return;
    int src, dst;
    if (e < EE) { src = clampN(ld_ei(ei, e)); dst = clampN(ld_ei(ei, EE + e)); }
    else        { src = e - EE;               dst = e - EE; }
    int pos = atomicAdd(&g_cur[dst], 1);
    if (pos >= 0 && pos < ET) g_srcS[pos] = src;
}

// ---------------------------------------------------------------------------
// Weight prep: pack W (KxM fp32) into fragment-major hi/lo [kb][nb][64]
// ---------------------------------------------------------------------------
__global__ void k_wprep(const float* __restrict__ W, uint32_t* __restrict__ Bh,
                        uint32_t* __restrict__ Bl, int KB16, int M) {
    int idx = blockIdx.x * blockDim.x + threadIdx.x;
    int NB = M >> 3;
    if (idx >= KB16 * NB * 64) return;
    int block = idx >> 6, r = idx & 63;
    int lane = r >> 1, slot = r & 1;
    int kb = block / NB, nb = block - kb * NB;
    int coll = lane >> 2, tg = lane & 3;
    int c8 = tg + slot * 4;
    int k2 = kb * 8 + c8;
    int m = nb * 8 + coll;
    float a0 = W[(size_t)(2 * k2) * M + m];
    float a1 = W[(size_t)(2 * k2 + 1) * M + m];
    uint32_t ph, pl;
    split_pack(a0, a1, ph, pl);
    Bh[idx] = ph;
    Bl[idx] = pl;
}

// ---------------------------------------------------------------------------
// Layer-1 algebraic path
// ---------------------------------------------------------------------------
__global__ void k_wsd(const float* __restrict__ W1, const float* __restrict__ a1s,
                      const float* __restrict__ a1d) {
    int t = threadIdx.x;
    if (t >= 88) return;
    int k = t / 8, h = t % 8;
    float ss = 0.f, sd = 0.f;
    const float* wrow = W1 + k * 1024 + h * 128;
    const float* asr  = a1s + h * 128;
    const float* adr  = a1d + h * 128;
    for (int c = 0; c < 128; c++) {
        float w = wrow[c];
        ss += w * asr[c];
        sd += w * adr[c];
    }
    g_ws[k * 8 + h] = ss;
    g_wd[k * 8 + h] = sd;
}

__global__ void k_alx(const float* __restrict__ x) {
    __shared__ float ws[88], wd[88];
    int t = threadIdx.x;
    if (t < 88) { ws[t] = g_ws[t]; wd[t] = g_wd[t]; }
    __syncthreads();
    int n = blockIdx.x * blockDim.x + t;
    if (n >= NN) return;
    float xv[11];
#pragma unroll
    for (int k = 0; k < 11; k++) xv[k] = x[n * 11 + k];
#pragma unroll
    for (int h = 0; h < 8; h++) {
        float ps = 0.f, pd = 0.f;
#pragma unroll
        for (int k = 0; k < 11; k++) {
            ps += xv[k] * ws[k * 8 + h];
            pd += xv[k] * wd[k * 8 + h];
        }
        g_als[n * 8 + h] = ps;
        g_ald[n * 8 + h] = pd;
    }
}

// softmax stats: pass1 gathers e into alpha (then max), pass2 coalesced exp.
template <int H>
__global__ void k_stats(const float* __restrict__ als, const float* __restrict__ ald,
                        float* __restrict__ dinv, float* __restrict__ alpha) {
    int idx = blockIdx.x * blockDim.x + threadIdx.x;
    if (idx >= NN * H) return;
    int n = idx / H, hh = idx - n * H;
    float ad = ald[idx];
    int s0 = g_off[n], s1 = g_off[n + 1];
    float m = -FLT_MAX;
    for (int j = s0; j < s1; j++) {
        float e = als[g_srcS[j] * H + hh] + ad;
        e = fmaxf(e, 0.2f * e);
        alpha[(size_t)j * H + hh] = e;
        m = fmaxf(m, e);
    }
    float ssum = 0.f;
    for (int j = s0; j < s1; j++) {
        float ex = __expf(alpha[(size_t)j * H + hh] - m);
        alpha[(size_t)j * H + hh] = ex;
        ssum += ex;
    }
    dinv[idx] = 1.f / (ssum + 1e-16f);
}

// Layer-1 aggregation: warp per node
__global__ void k_aggx(const float* __restrict__ x) {
    int gw = (blockIdx.x * blockDim.x + threadIdx.x) >> 5;
    if (gw >= NN) return;
    int lane = threadIdx.x & 31;
    int n = gw;
    float dv = (lane < 8) ? g_dinv[n * 8 + lane] : 0.f;
    int i0 = lane, i1 = lane + 32, i2 = lane + 64;
    int h0 = i0 / 11, k0 = i0 - h0 * 11;
    int h1 = i1 / 11, k1 = i1 - h1 * 11;
    bool v2 = (i2 < 88);
    int h2 = v2 ? i2 / 11 : 0, k2 = v2 ? i2 - (i2 / 11) * 11 : 0;
    float z0 = 0.f, z1 = 0.f, z2 = 0.f;
    int s0 = g_off[n], s1 = g_off[n + 1];
    for (int j = s0; j < s1; j++) {
        int src = g_srcS[j];
        float xv = (lane < 11) ? x[src * 11 + lane] : 0.f;
        float av = (lane < 8) ? g_alpha[(size_t)j * 8 + lane] * dv : 0.f;
        float a0 = __shfl_sync(0xFFFFFFFFu, av, h0);
        float x0 = __shfl_sync(0xFFFFFFFFu, xv, k0);
        float a1 = __shfl_sync(0xFFFFFFFFu, av, h1);
        float x1 = __shfl_sync(0xFFFFFFFFu, xv, k1);
        float a2 = __shfl_sync(0xFFFFFFFFu, av, h2);
        float x2 = __shfl_sync(0xFFFFFFFFu, xv, k2);
        z0 += a0 * x0;
        z1 += a1 * x1;
        if (v2) z2 += a2 * x2;
    }
    g_z[(size_t)n * 88 + i0] = z0;
    g_z[(size_t)n * 88 + i1] = z1;
    if (v2) g_z[(size_t)n * 88 + i2] = z2;
}

// o1 projection; emits fragment-major bf16 hi/lo (A of GEMM2, KB16=64)
__global__ __launch_bounds__(256) void k_proj(const float* __restrict__ W1,
                                              const float* __restrict__ b1,
                                              uint32_t* __restrict__ oh,
                                              uint32_t* __restrict__ ol) {
    __shared__ float Wh[11][128];
    __shared__ float zt[64][11];
    int n0 = blockIdx.x * 64;
    int h = blockIdx.y;
    int t = threadIdx.x;
    for (int i = t; i < 11 * 128; i += 256) {
        int k = i >> 7, c = i & 127;
        Wh[k][c] = W1[k * 1024 + h * 128 + c];
    }
    for (int i = t; i < 64 * 11; i += 256) {
        int r = i / 11, k = i - r * 11;
        int n = n0 + r;
        zt[r][k] = (n < NN) ? g_z[(size_t)n * 88 + h * 11 + k] : 0.f;
    }
    __syncthreads();
    int c = t & 63;
    int rg = t >> 6;
    float bias0 = b1[h * 128 + 2 * c];
    float bias1 = b1[h * 128 + 2 * c + 1];
    int cg = h * 64 + c;
#pragma unroll 4
    for (int i = 0; i < 16; i++) {
        int r = rg * 16 + i;
        int n = n0 + r;
        if (n >= NN) break;
        float a0 = bias0, a1 = bias1;
#pragma unroll
        for (int k = 0; k < 11; k++) {
            float zz = zt[r][k];
            a0 += zz * Wh[k][2 * c];
            a1 += zz * Wh[k][2 * c + 1];
        }
        a0 = (a0 > 0.f) ? a0 : 0.01f * a0;
        a1 = (a1 > 0.f) ? a1 : 0.01f * a1;
        uint32_t ph, pl;
        split_pack(a0, a1, ph, pl);
        size_t idx = a_frag_idx(n, cg, 64);
        oh[idx] = ph;
        ol[idx] = pl;
    }
}

// ---------------------------------------------------------------------------
// bf16x3 tensor-core GEMM + fused al_s/al_d epilogue reduction.
// __launch_bounds__(256, 2): cap regs at 128 -> 2 CTAs/SM for latency hiding.
// ---------------------------------------------------------------------------
#define GEMM_SMEM (16384 * 4)

__device__ __forceinline__ void mma_bf16(float* c, const uint32_t* a, const uint32_t* b) {
    asm volatile(
        "mma.sync.aligned.m16n8k16.row.col.f32.bf16.bf16.f32 "
        "{%0,%1,%2,%3}, {%4,%5,%6,%7}, {%8,%9}, {%0,%1,%2,%3};"
        : "+f"(c[0]), "+f"(c[1]), "+f"(c[2]), "+f"(c[3])
        : "r"(a[0]), "r"(a[1]), "r"(a[2]), "r"(a[3]), "r"(b[0]), "r"(b[1]));
}

__device__ __forceinline__ void cp16(uint32_t dst, const void* src) {
    asm volatile("cp.async.cg.shared.global [%0], [%1], 16;"
                 :: "r"(dst), "l"(src));
}

__global__ __launch_bounds__(256, 2) void k_gemm_bf16(const uint32_t* __restrict__ Ahp,
                                                      const uint32_t* __restrict__ Alp,
                                                      const uint32_t* __restrict__ Bhp,
                                                      const uint32_t* __restrict__ Blp,
                                                      float* __restrict__ C,
                                                      const float* __restrict__ a_s,
                                                      const float* __restrict__ a_d,
                                                      float* __restrict__ als,
                                                      float* __restrict__ ald,
                                                      int Nrows, int K, int M,
                                                      int Cph, int H) {
    extern __shared__ uint32_t smem[];
    int tid = threadIdx.x;
    int lane = tid & 31, warp = tid >> 5;
    int g = lane >> 2, tg = lane & 3;
    int rowBase = blockIdx.x * 128;
    int colBase = blockIdx.y * 128;
    int warpM = (warp & 1) * 64;
    int warpN = (warp >> 1) * 32;
    int mbw = (warp & 1) * 4;
    int nbw = (warp >> 1) * 4;
    int KB16 = K >> 4;
    int NB = M >> 3;
    int mb0 = blockIdx.x * 8;
    int nb0 = blockIdx.y * 16;

    int ablk = tid >> 4;
    int akb  = ablk >> 3;
    int amb  = ablk & 7;
    int aj   = (tid & 15) * 8;
    size_t abase = (size_t)(mb0 + amb) * KB16 * 128 + aj;
    int bblk = tid >> 3;
    int bkb  = bblk >> 4;
    int bnb  = bblk & 15;
    int bj   = (tid & 7) * 8;
    size_t bbase = (size_t)(nb0 + bnb) * 64 + bj;

    uint32_t smemBase = (uint32_t)__cvta_generic_to_shared(smem);
    uint32_t AhD[2], AlD[2], BhD[2], BlD[2];
#pragma unroll
    for (int buf = 0; buf < 2; buf++) {
        AhD[buf] = smemBase + (buf * 2048 + tid * 8) * 4;
        AlD[buf] = smemBase + (4096 + buf * 2048 + tid * 8) * 4;
        BhD[buf] = smemBase + (8192 + buf * 2048 + tid * 8) * 4;
        BlD[buf] = smemBase + (12288 + buf * 2048 + tid * 8) * 4;
    }

    float acc[4][4][4];
#pragma unroll
    for (int mt = 0; mt < 4; mt++)
#pragma unroll
        for (int nt = 0; nt < 4; nt++)
#pragma unroll
            for (int i = 0; i < 4; i++) acc[mt][nt][i] = 0.f;

    const int NT = K >> 5;

    auto issue = [&](int t, int buf) {
        const uint32_t* ah = Ahp + abase + (size_t)(t * 2 + akb) * 128;
        const uint32_t* al = Alp + abase + (size_t)(t * 2 + akb) * 128;
        cp16(AhD[buf],      ah);
        cp16(AhD[buf] + 16, ah + 4);
        cp16(AlD[buf],      al);
        cp16(AlD[buf] + 16, al + 4);
        const uint32_t* bh = Bhp + (size_t)(t * 2 + bkb) * NB * 64 + bbase;
        const uint32_t* bl = Blp + (size_t)(t * 2 + bkb) * NB * 64 + bbase;
        cp16(BhD[buf],      bh);
        cp16(BhD[buf] + 16, bh + 4);
        cp16(BlD[buf],      bl);
        cp16(BlD[buf] + 16, bl + 4);
    };

    issue(0, 0);
    asm volatile("cp.async.commit_group;");

    for (int t = 0; t < NT; t++) {
        if (t + 1 < NT) issue(t + 1, (t + 1) & 1);
        asm volatile("cp.async.commit_group;");
        asm volatile("cp.async.wait_group 1;");
        __syncthreads();

        const uint32_t* As_h = smem + (t & 1) * 2048;
        const uint32_t* As_l = smem + 4096 + (t & 1) * 2048;
        const uint32_t* Bs_h = smem + 8192 + (t & 1) * 2048;
        const uint32_t* Bs_l = smem + 12288 + (t & 1) * 2048;

#pragma unroll
        for (int kk = 0; kk < 2; kk++) {
            uint4 ah4[4], al4[4];
#pragma unroll
            for (int mt = 0; mt < 4; mt++) {
                int bofs = (kk * 8 + mbw + mt) * 128 + lane * 4;
                ah4[mt] = *(const uint4*)&As_h[bofs];
                al4[mt] = *(const uint4*)&As_l[bofs];
            }
#pragma unroll
            for (int nt = 0; nt < 4; nt++) {
                int bofs = (kk * 16 + nbw + nt) * 64 + lane * 2;
                uint2 bh2 = *(const uint2*)&Bs_h[bofs];
                uint2 bl2 = *(const uint2*)&Bs_l[bofs];
                uint32_t bh[2] = {bh2.x, bh2.y};
                uint32_t bl[2] = {bl2.x, bl2.y};
#pragma unroll
                for (int mt = 0; mt < 4; mt++) {
                    mma_bf16(acc[mt][nt], (const uint32_t*)&ah4[mt], bh);
                    mma_bf16(acc[mt][nt], (const uint32_t*)&ah4[mt], bl);
                    mma_bf16(acc[mt][nt], (const uint32_t*)&al4[mt], bh);
                }
            }
        }
        __syncthreads();
    }

    // ---- store C + fused al reduction ----
    int head = (colBase + warpN) / Cph;
    float ps0[4] = {0, 0, 0, 0}, ps1[4] = {0, 0, 0, 0};
    float pd0[4] = {0, 0, 0, 0}, pd1[4] = {0, 0, 0, 0};

#pragma unroll
    for (int nt = 0; nt < 4; nt++) {
        int cc = colBase + warpN + nt * 8 + tg * 2;
        float s0 = a_s[cc], s1 = a_s[cc + 1];
        float d0 = a_d[cc], d1 = a_d[cc + 1];
#pragma unroll
        for (int mt = 0; mt < 4; mt++) {
            int r = rowBase + warpM + mt * 16 + g;
            if (r < Nrows)
                *(float2*)&C[(size_t)r * M + cc] = make_float2(acc[mt][nt][0], acc[mt][nt][1]);
            if (r + 8 < Nrows)
                *(float2*)&C[(size_t)(r + 8) * M + cc] = make_float2(acc[mt][nt][2], acc[mt][nt][3]);
            ps0[mt] += acc[mt][nt][0] * s0 + acc[mt][nt][1] * s1;
            ps1[mt] += acc[mt][nt][2] * s0 + acc[mt][nt][3] * s1;
            pd0[mt] += acc[mt][nt][0] * d0 + acc[mt][nt][1] * d1;
            pd1[mt] += acc[mt][nt][2] * d0 + acc[mt][nt][3] * d1;
        }
    }
#pragma unroll
    for (int mt = 0; mt < 4; mt++) {
        ps0[mt] += __shfl_xor_sync(0xFFFFFFFFu, ps0[mt], 1);
        ps0[mt] += __shfl_xor_sync(0xFFFFFFFFu, ps0[mt], 2);
        ps1[mt] += __shfl_xor_sync(0xFFFFFFFFu, ps1[mt], 1);
        ps1[mt] += __shfl_xor_sync(0xFFFFFFFFu, ps1[mt], 2);
        pd0[mt] += __shfl_xor_sync(0xFFFFFFFFu, pd0[mt], 1);
        pd0[mt] += __shfl_xor_sync(0xFFFFFFFFu, pd0[mt], 2);
        pd1[mt] += __shfl_xor_sync(0xFFFFFFFFu, pd1[mt], 1);
        pd1[mt] += __shfl_xor_sync(0xFFFFFFFFu, pd1[mt], 2);
    }
    if (tg == 0) {
#pragma unroll
        for (int mt = 0; mt < 4; mt++) {
            int r = rowBase + warpM + mt * 16 + g;
            if (r < Nrows) {
                atomicAdd(&als[r * H + head], ps0[mt]);
                atomicAdd(&ald[r * H + head], pd0[mt]);
            }
            if (r + 8 < Nrows) {
                atomicAdd(&als[(r + 8) * H + head], ps1[mt]);
                atomicAdd(&ald[(r + 8) * H + head], pd1[mt]);
            }
        }
    }
}

// ---------------------------------------------------------------------------
// Aggregation: WARP per node, chunked operand prefetch.
// PACK=true: emit fragment-major bf16 hi/lo (KBLK kblocks).
// ---------------------------------------------------------------------------
template <int OUT, int H, int C, bool PACK, int KBLK>
__global__ void k_aggw(const float* __restrict__ h, const float* __restrict__ alpha,
                       const float* __restrict__ dinv, const float* __restrict__ bias,
                       float* __restrict__ outF, uint32_t* __restrict__ outH,
                       uint32_t* __restrict__ outL) {
    constexpr int J = OUT / 128;
    constexpr int EC = 32 / H;
    int n = (blockIdx.x * blockDim.x + threadIdx.x) >> 5;
    if (n >= NN) return;
    int lane = threadIdx.x & 31;

    float dv = (lane < H) ? dinv[n * H + lane] : 0.f;
    int hh = lane & (H - 1);
    int eoff = lane / H;
    float dvh = __shfl_sync(0xFFFFFFFFu, dv, hh);

    int headOf[J];
#pragma unroll
    for (int j = 0; j < J; j++) headOf[j] = (4 * lane + 128 * j) / C;

    float4 acc[J];
#pragma unroll
    for (int j = 0; j < J; j++) acc[j] = make_float4(0.f, 0.f, 0.f, 0.f);

    int s0 = g_off[n], s1 = g_off[n + 1];
    for (int e0 = s0; e0 < s1; e0 += EC) {
        int cnt = min(EC, s1 - e0);
        int srcl = (lane < cnt) ? g_srcS[e0 + lane] : 0;
        float av = (eoff < cnt) ? alpha[(size_t)e0 * H + lane] * dvh : 0.f;
        for (int i = 0; i < cnt; i++) {
            int src = __shfl_sync(0xFFFFFFFFu, srcl, i);
            const float4* hp = (const float4*)(h + (size_t)src * OUT) + lane;
#pragma unroll
            for (int j = 0; j < J; j++) {
                float a = __shfl_sync(0xFFFFFFFFu, av, i * H + headOf[j]);
                float4 hv = hp[32 * j];
                acc[j].x += a * hv.x;
                acc[j].y += a * hv.y;
                acc[j].z += a * hv.z;
                acc[j].w += a * hv.w;
            }
        }
    }

#pragma unroll
    for (int j = 0; j < J; j++) {
        int c0 = 4 * lane + 128 * j;
        float v0 = acc[j].x + bias[c0];
        float v1 = acc[j].y + bias[c0 + 1];
        float v2 = acc[j].z + bias[c0 + 2];
        float v3 = acc[j].w + bias[c0 + 3];
        v0 = (v0 > 0.f) ? v0 : 0.01f * v0;
        v1 = (v1 > 0.f) ? v1 : 0.01f * v1;
        v2 = (v2 > 0.f) ? v2 : 0.01f * v2;
        v3 = (v3 > 0.f) ? v3 : 0.01f * v3;
        if constexpr (PACK) {
            uint32_t ph0, pl0, ph1, pl1;
            split_pack(v0, v1, ph0, pl0);
            split_pack(v2, v3, ph1, pl1);
            int t0 = c0 >> 1;
            size_t i0 = a_frag_idx(n, t0, KBLK);
            size_t i1 = a_frag_idx(n, t0 + 1, KBLK);
            outH[i0] = ph0; outL[i0] = pl0;
            outH[i1] = ph1; outL[i1] = pl1;
        } else {
            *(float4*)&outF[(size_t)n * OUT + c0] = make_float4(v0, v1, v2, v3);
        }
    }
}

// ---------------------------------------------------------------------------
// Pooling + head
// ---------------------------------------------------------------------------
__device__ __forceinline__ int lower_bound_b(const int* __restrict__ b, int val) {
    int lo = 0, hi = NN;
    while (lo < hi) {
        int mid = (lo + hi) >> 1;
        if (ld_b(b, mid) < val) lo = mid + 1; else hi = mid;
    }
    return lo;
}

__global__ void k_poolseg(const int* __restrict__ batch, const float* __restrict__ o3,
                          const float* __restrict__ Wout, const float* __restrict__ bout,
                          float* __restrict__ out) {
    int gph = blockIdx.x, t = threadIdx.x;
    int lo = lower_bound_b(batch, gph);
    int hi = lower_bound_b(batch, gph + 1);
    float s = 0.f;
    for (int n = lo; n < hi; n++) s += o3[(size_t)n * 128 + t];
    float cnt = fmaxf((float)(hi - lo), 1.f);
    float v = (s / cnt) * Wout[t];
#pragma unroll
    for (int o = 16; o > 0; o >>= 1) v += __shfl_down_sync(0xFFFFFFFFu, v, o);
    __shared__ float red[4];
    if ((t & 31) == 0) red[t >> 5] = v;
    __syncthreads();
    if (t == 0) out[gph] = red[0] + red[1] + red[2] + red[3] + bout[0];
}

// ---------------------------------------------------------------------------
// Launch
// ---------------------------------------------------------------------------
extern "C" void kernel_launch(void* const* d_in, const int* in_sizes, int n_in,
                              void* d_out, int out_size) {
    int ix = 0, iei = 1, ib = 2, iW1 = 3, ia1s = 4, ia1d = 5, ib1 = 6,
        iW2 = 7, ia2s = 8, ia2d = 9, ib2 = 10, iW3 = 11, ia3s = 12,
        ia3d = 13, ib3 = 14, iWout = 15, ibout = 16;
    {
        int jx = -1, jei = -1, jb = -1, jW1 = -1, jW2 = -1, jW3 = -1, jbout = -1;
        int j1024[3], n1024 = 0;
        int j512[3],  n512 = 0;
        int j128[4],  n128 = 0;
        bool clean = true;
        for (int i = 0; i < n_in; i++) {
            int s = in_sizes[i];
            if      (s == 550000) { if (jx >= 0) clean = false; jx = i; }
            else if (s == 500000) { if (jei >= 0) clean = false; jei = i; }
            else if (s == 50000)  { if (jb >= 0) clean = false; jb = i; }
            else if (s == 11264)  { if (jW1 >= 0) clean = false; jW1 = i; }
            else if (s == 524288) { if (jW2 >= 0) clean = false; jW2 = i; }
            else if (s == 65536)  { if (jW3 >= 0) clean = false; jW3 = i; }
            else if (s == 1024)   { if (n1024 < 3) j1024[n1024] = i; n1024++; }
            else if (s == 512)    { if (n512  < 3) j512[n512]   = i; n512++; }
            else if (s == 128)    { if (n128  < 4) j128[n128]   = i; n128++; }
            else if (s == 1)      { if (jbout >= 0) clean = false; jbout = i; }
            else clean = false;
        }
        if (clean && jx >= 0 && jei >= 0 && jb >= 0 && jW1 >= 0 && jW2 >= 0 &&
            jW3 >= 0 && jbout >= 0 && n1024 == 3 && n512 == 3 && n128 == 4) {
            ix = jx; iei = jei; ib = jb; iW1 = jW1; iW2 = jW2; iW3 = jW3;
            ia1s = j1024[0]; ia1d = j1024[1]; ib1 = j1024[2];
            ia2s = j512[0];  ia2d = j512[1];  ib2 = j512[2];
            ia3s = j128[0];  ia3d = j128[1];  ib3 = j128[2]; iWout = j128[3];
            ibout = jbout;
        }
    }

    const float* x    = (const float*)d_in[ix];
    const int*   ei   = (const int*)d_in[iei];
    const int*   batch= (const int*)d_in[ib];
    const float* W1   = (const float*)d_in[iW1];
    const float* a1s  = (const float*)d_in[ia1s];
    const float* a1d  = (const float*)d_in[ia1d];
    const float* b1   = (const float*)d_in[ib1];
    const float* W2   = (const float*)d_in[iW2];
    const float* a2s  = (const float*)d_in[ia2s];
    const float* a2d  = (const float*)d_in[ia2d];
    const float* b2   = (const float*)d_in[ib2];
    const float* W3   = (const float*)d_in[iW3];
    const float* a3s  = (const float*)d_in[ia3s];
    const float* a3d  = (const float*)d_in[ia3d];
    const float* b3   = (const float*)d_in[ib3];
    const float* Wout = (const float*)d_in[iWout];
    const float* bout = (const float*)d_in[ibout];
    float* out = (float*)d_out;

    float* P = nullptr;      cudaGetSymbolAddress((void**)&P, g_P);
    uint32_t* Qh = nullptr;  cudaGetSymbolAddress((void**)&Qh, g_Qh);
    uint32_t* Ql = nullptr;  cudaGetSymbolAddress((void**)&Ql, g_Ql);
    uint32_t* B2h = nullptr; cudaGetSymbolAddress((void**)&B2h, g_B2h);
    uint32_t* B2l = nullptr; cudaGetSymbolAddress((void**)&B2l, g_B2l);
    uint32_t* B3h = nullptr; cudaGetSymbolAddress((void**)&B3h, g_B3h);
    uint32_t* B3l = nullptr; cudaGetSymbolAddress((void**)&B3l, g_B3l);
    float* als = nullptr;    cudaGetSymbolAddress((void**)&als, g_als);
    float* ald = nullptr;    cudaGetSymbolAddress((void**)&ald, g_ald);
    float* dinv = nullptr;   cudaGetSymbolAddress((void**)&dinv, g_dinv);
    float* alpha = nullptr;  cudaGetSymbolAddress((void**)&alpha, g_alpha);

    static bool init_done = false;
    static cudaStream_t s1;
    static cudaEvent_t evFork, evJoin;
    if (!init_done) {
        cudaFuncSetAttribute(k_gemm_bf16, cudaFuncAttributeMaxDynamicSharedMemorySize,
                             GEMM_SMEM);
        cudaStreamCreateWithFlags(&s1, cudaStreamNonBlocking);
        cudaEventCreateWithFlags(&evFork, cudaEventDisableTiming);
        cudaEventCreateWithFlags(&evJoin, cudaEventDisableTiming);
        init_done = true;
    }

    // ---- fork: independent prep on s1 (weights + layer-1 attention coefs) ----
    cudaEventRecord(evFork, 0);
    cudaStreamWaitEvent(s1, evFork, 0);
    k_wprep<<<(64 * 64 * 64 + 255) / 256, 256, 0, s1>>>(W2, B2h, B2l, 64, 512);
    k_wprep<<<(32 * 16 * 64 + 255) / 256, 256, 0, s1>>>(W3, B3h, B3l, 32, 128);
    k_wsd<<<1, 128, 0, s1>>>(W1, a1s, a1d);
    k_alx<<<(NN + 255) / 256, 256, 0, s1>>>(x);

    // ---- stream 0: dtype detection + CSR build ----
    k_detect<<<1, 1024>>>(ei, batch);
    k_zero_deg<<<(NN + 255) / 256, 256>>>();
    k_count<<<(ET + 255) / 256, 256>>>(ei);
    k_scan1<<<50, 1024>>>();
    k_scan2<<<1, 32>>>();
    k_scan3<<<50, 1024>>>();
    k_scatter<<<(ET + 255) / 256, 256>>>(ei);

    // ---- join ----
    cudaEventRecord(evJoin, s1);
    cudaStreamWaitEvent(0, evJoin, 0);

    // ---- Layer 1 (algebraic): o1 -> Qh/Ql fragment-major ----
    k_stats<8><<<(NN * 8 + 255) / 256, 256>>>(als, ald, dinv, alpha);
    k_aggx<<<(NN * 32 + 255) / 256, 256>>>(x);
    {
        dim3 grid((NN + 63) / 64, 8);
        k_proj<<<grid, 256>>>(W1, b1, Qh, Ql);
    }

    // ---- Layer 2: GEMM (+ fused al), stats, agg ----
    cudaMemsetAsync(als, 0, NN * 8 * sizeof(float));
    cudaMemsetAsync(ald, 0, NN * 8 * sizeof(float));
    {
        dim3 grid((NN + 127) / 128, 4);
        k_gemm_bf16<<<grid, 256, GEMM_SMEM>>>(Qh, Ql, B2h, B2l, P,
                                              a2s, a2d, als, ald,
                                              NN, 1024, 512, 64, 8);
        k_stats<8><<<(NN * 8 + 255) / 256, 256>>>(als, ald, dinv, alpha);
        k_aggw<512, 8, 64, true, 32><<<(NN * 32 + 255) / 256, 256>>>(
            P, alpha, dinv, b2, nullptr, Qh, Ql);
    }

    // ---- Layer 3: GEMM (+ fused al), stats, agg ----
    cudaMemsetAsync(als, 0, NN * 4 * sizeof(float));
    cudaMemsetAsync(ald, 0, NN * 4 * sizeof(float));
    {
        dim3 grid((NN + 127) / 128, 1);
        k_gemm_bf16<<<grid, 256, GEMM_SMEM>>>(Qh, Ql, B3h, B3l, P,
                                              a3s, a3d, als, ald,
                                              NN, 512, 128, 32, 4);
        k_stats<4><<<(NN * 4 + 255) / 256, 256>>>(als, ald, dinv, alpha);
        k_aggw<128, 4, 32, false, 0><<<(NN * 32 + 255) / 256, 256>>>(
            P, alpha, dinv, b3, (float*)Qh, nullptr, nullptr);
    }

    // ---- Pool + head ----
    k_poolseg<<<NG, 128>>>(batch, (float*)Qh, Wout, bout, out);
}